// round 9
// baseline (speedup 1.0000x reference)
#include <cuda_runtime.h>
#include <math.h>
#include <stdint.h>

// Problem dims
#define D   768
#define H   12
#define SQ  256
#define BB  8
#define DH  64
#define M   (BB*SQ)     // 2048 rows
#define FF  (4*D)       // 3072
#define MD  ((size_t)M*D)

// ---------------- scratch (device globals; no allocs allowed) ----------------
__device__ float g_x[M*D];
__device__ float g_y[M*D];
__device__ float g_qkv[3*M*D];            // [3][B,H,S,DH]
__device__ float g_h[M*D];                // attn/ffn2 output [B,S,D]
__device__ float g_ffn[(size_t)M*FF];     // ffn hidden

// ---------------- tf32 helpers ----------------
__device__ __forceinline__ float to_tf32(float x) {
    float r;
    asm("cvt.rna.tf32.f32 %0, %1;" : "=f"(r) : "f"(x));
    return r;
}

__device__ __forceinline__ void mma8(float c[4],
    uint32_t a0, uint32_t a1, uint32_t a2, uint32_t a3,
    uint32_t b0, uint32_t b1)
{
    asm volatile(
        "mma.sync.aligned.m16n8k8.row.col.f32.tf32.tf32.f32 "
        "{%0,%1,%2,%3}, {%4,%5,%6,%7}, {%8,%9}, {%0,%1,%2,%3};"
        : "+f"(c[0]), "+f"(c[1]), "+f"(c[2]), "+f"(c[3])
        : "r"(a0), "r"(a1), "r"(a2), "r"(a3), "r"(b0), "r"(b1));
}

__device__ __forceinline__ float gelu_exact(float v) {
    return 0.5f * v * (1.0f + erff(v * 0.70710678118654752f));
}

// ============================================================================
// Double-buffered tf32 GEMM.  Block tile 128 x BN, BK=32, 256 threads,
// 8 warps as 2(m) x 4(n):  warp tile 64 x (BN/4).
// MODE: 0 = plain+bias, 1 = bias+GELU, 2 = QKV fused (A per matrix, scatter).
// ============================================================================
template<int BN, int MODE>
__global__ __launch_bounds__(256) void gemm_db(
    const float* __restrict__ Aq, const float* __restrict__ Akv,
    const float* __restrict__ W, const float* __restrict__ bias,
    float* __restrict__ C, int N, int K)
{
    constexpr int BP = BN + 8;
    constexpr int NF = BN / 32;
    constexpr int WN = BN / 4;
    constexpr int NB4 = (32 * BN / 4) / 256;
    constexpr int ASZ = 128 * 36;
    constexpr int BSZ = 32 * BP;

    extern __shared__ float smem[];
    float* sA = smem;
    float* sB = smem + 2 * ASZ;

    const int tid = threadIdx.x;
    const int lane = tid & 31, warp = tid >> 5;
    const int wm = warp >> 2, wn = warp & 3;
    const int g = lane >> 2, tg = lane & 3;
    const int row0 = blockIdx.y * 128;

    const float* A; const float* Wp; const float* bp; float* Cp; int col0;
    if (MODE == 2) {
        const int perMat = 768 / BN;
        const int mat = blockIdx.x / perMat;
        col0 = (blockIdx.x % perMat) * BN;
        A  = (mat == 0) ? Aq : Akv;
        Wp = W + (size_t)mat * D * D;
        bp = bias + mat * D;
        Cp = C + (size_t)mat * MD;
    } else {
        col0 = blockIdx.x * BN;
        A = Aq; Wp = W; bp = bias; Cp = C;
    }

    float acc[4][NF][4] = {};
    float4 ar[4], br[NB4];

    #define LOAD_A(K0) { \
        _Pragma("unroll") \
        for (int j = 0; j < 4; j++) { \
            int f = tid + 256 * j; \
            int r = f >> 3, c4 = (f & 7) << 2; \
            ar[j] = *(const float4*)&A[(size_t)(row0 + r) * K + (K0) + c4]; \
        } }
    #define LOAD_B(K0) { \
        _Pragma("unroll") \
        for (int j = 0; j < NB4; j++) { \
            int f = tid + 256 * j; \
            int r = f / (BN / 4), c4 = (f % (BN / 4)) << 2; \
            br[j] = *(const float4*)&Wp[(size_t)((K0) + r) * N + col0 + c4]; \
        } }
    #define STS_AB(BUF) { \
        _Pragma("unroll") \
        for (int j = 0; j < 4; j++) { \
            int f = tid + 256 * j; \
            int r = f >> 3, c4 = (f & 7) << 2; \
            float* p = &sA[(BUF) * ASZ + r * 36 + c4]; \
            p[0] = to_tf32(ar[j].x); p[1] = to_tf32(ar[j].y); \
            p[2] = to_tf32(ar[j].z); p[3] = to_tf32(ar[j].w); \
        } \
        _Pragma("unroll") \
        for (int j = 0; j < NB4; j++) { \
            int f = tid + 256 * j; \
            int r = f / (BN / 4), c4 = (f % (BN / 4)) << 2; \
            float* p = &sB[(BUF) * BSZ + r * BP + c4]; \
            p[0] = to_tf32(br[j].x); p[1] = to_tf32(br[j].y); \
            p[2] = to_tf32(br[j].z); p[3] = to_tf32(br[j].w); \
        } }

    LOAD_A(0); LOAD_B(0);
    STS_AB(0);
    __syncthreads();

    int buf = 0;
    for (int k0 = 0; k0 < K; k0 += 32) {
        const bool more = (k0 + 32 < K);
        if (more) { LOAD_A(k0 + 32); LOAD_B(k0 + 32); }

        const float* cA = &sA[buf * ASZ];
        const float* cB = &sB[buf * BSZ];
        #pragma unroll
        for (int ks = 0; ks < 4; ks++) {
            const int k8 = ks * 8;
            uint32_t a[4][4], b[NF][2];
            #pragma unroll
            for (int mf = 0; mf < 4; mf++) {
                int m0 = wm * 64 + mf * 16 + g;
                a[mf][0] = __float_as_uint(cA[m0 * 36 + k8 + tg]);
                a[mf][1] = __float_as_uint(cA[(m0 + 8) * 36 + k8 + tg]);
                a[mf][2] = __float_as_uint(cA[m0 * 36 + k8 + tg + 4]);
                a[mf][3] = __float_as_uint(cA[(m0 + 8) * 36 + k8 + tg + 4]);
            }
            #pragma unroll
            for (int nf = 0; nf < NF; nf++) {
                int n0 = wn * WN + nf * 8 + g;
                b[nf][0] = __float_as_uint(cB[(k8 + tg) * BP + n0]);
                b[nf][1] = __float_as_uint(cB[(k8 + tg + 4) * BP + n0]);
            }
            #pragma unroll
            for (int mf = 0; mf < 4; mf++)
                #pragma unroll
                for (int nf = 0; nf < NF; nf++)
                    mma8(acc[mf][nf], a[mf][0], a[mf][1], a[mf][2], a[mf][3],
                         b[nf][0], b[nf][1]);
        }

        if (more) {
            STS_AB(buf ^ 1);
            __syncthreads();
            buf ^= 1;
        }
    }

    #undef LOAD_A
    #undef LOAD_B
    #undef STS_AB

    #pragma unroll
    for (int mf = 0; mf < 4; mf++) {
        int r_lo = row0 + wm * 64 + mf * 16 + g;
        #pragma unroll
        for (int nf = 0; nf < NF; nf++) {
            int c = col0 + wn * WN + nf * 8 + tg * 2;
            float b0 = bp[c], b1 = bp[c + 1];
            float v00 = acc[mf][nf][0] + b0, v01 = acc[mf][nf][1] + b1;
            float v10 = acc[mf][nf][2] + b0, v11 = acc[mf][nf][3] + b1;
            if (MODE == 1) {
                v00 = gelu_exact(v00); v01 = gelu_exact(v01);
                v10 = gelu_exact(v10); v11 = gelu_exact(v11);
            }
            if (MODE == 2) {
                int hh = c >> 6, dh = c & 63;
                int b_0 = r_lo >> 8, s_0 = r_lo & 255;
                int b_1 = (r_lo + 8) >> 8, s_1 = (r_lo + 8) & 255;
                *(float2*)&Cp[(((size_t)b_0 * H + hh) * SQ + s_0) * DH + dh] = make_float2(v00, v01);
                *(float2*)&Cp[(((size_t)b_1 * H + hh) * SQ + s_1) * DH + dh] = make_float2(v10, v11);
            } else {
                *(float2*)&Cp[(size_t)r_lo * N + c] = make_float2(v00, v01);
                *(float2*)&Cp[(size_t)(r_lo + 8) * N + c] = make_float2(v10, v11);
            }
        }
    }
}

// ============================================================================
// Fused attention: scores (QK^T * 0.125 + mask) -> softmax -> P @ V -> out.
// One block = one (b,h) x 64-query tile. 256 threads, 8 warps (2m x 4n).
// smem: sQ[64][68] + sP[64][260] + sKV(max(64*68, 2*32*72)=4608 floats).
// K processed in 4 stages of 64 rows; V double-buffered in 32-row chunks.
// ============================================================================
#define PSTR 260
#define KVREG 4608
#define ATT_SMEM ((64*68 + 64*PSTR + KVREG) * (int)sizeof(float))

__global__ __launch_bounds__(256) void attn_fused(
    const float* __restrict__ QKV,   // [3][B,H,S,DH]
    const int* __restrict__ mask,    // [B,S]
    float* __restrict__ out)         // [B,S,D]
{
    extern __shared__ float smem[];
    float* sQ = smem;                 // [64][68]
    float* sP = smem + 64 * 68;       // [64][260]
    float* sKV = sP + 64 * PSTR;      // [64][68] (scores) / 2x[32][72] (PV)

    const int tid = threadIdx.x;
    const int lane = tid & 31, warp = tid >> 5;
    const int wm = warp >> 2, wn = warp & 3;     // 2 x 4 warps
    const int g = lane >> 2, tg = lane & 3;

    const int bh = blockIdx.x;
    const int b = bh / H, hh = bh % H;
    const int q0 = blockIdx.y * 64;

    const float* Qp = QKV + ((size_t)bh * SQ + q0) * DH;
    const float* Kp = QKV + MD + (size_t)bh * SQ * DH;
    const float* Vp = QKV + 2 * MD + (size_t)bh * SQ * DH;

    // ---- load Q tile (64 x 64), stride 68 ----
    #pragma unroll
    for (int j = 0; j < 4; j++) {
        int f = tid + 256 * j;
        int r = f >> 4, c4 = (f & 15) << 2;
        float4 v = *(const float4*)&Qp[(size_t)r * DH + c4];
        float* p = &sQ[r * 68 + c4];
        p[0] = to_tf32(v.x); p[1] = to_tf32(v.y);
        p[2] = to_tf32(v.z); p[3] = to_tf32(v.w);
    }

    // ---- scores: 4 stages of 64 key positions; warp n-tile = 16 ----
    for (int stage = 0; stage < 4; stage++) {
        const int n0base = stage * 64;
        __syncthreads();   // sKV reuse safe; also covers sQ on first stage
        #pragma unroll
        for (int j = 0; j < 4; j++) {
            int f = tid + 256 * j;
            int r = f >> 4, c4 = (f & 15) << 2;
            float4 v = *(const float4*)&Kp[(size_t)(n0base + r) * DH + c4];
            float* p = &sKV[r * 68 + c4];
            p[0] = to_tf32(v.x); p[1] = to_tf32(v.y);
            p[2] = to_tf32(v.z); p[3] = to_tf32(v.w);
        }
        __syncthreads();

        float acc[2][2][4] = {};
        #pragma unroll
        for (int ks = 0; ks < 8; ks++) {
            const int k8 = ks * 8;
            uint32_t a[2][4], bf[2][2];
            #pragma unroll
            for (int mf = 0; mf < 2; mf++) {
                int m0 = wm * 32 + mf * 16 + g;
                a[mf][0] = __float_as_uint(sQ[m0 * 68 + k8 + tg]);
                a[mf][1] = __float_as_uint(sQ[(m0 + 8) * 68 + k8 + tg]);
                a[mf][2] = __float_as_uint(sQ[m0 * 68 + k8 + tg + 4]);
                a[mf][3] = __float_as_uint(sQ[(m0 + 8) * 68 + k8 + tg + 4]);
            }
            #pragma unroll
            for (int nf = 0; nf < 2; nf++) {
                int n0 = wn * 16 + nf * 8 + g;
                bf[nf][0] = __float_as_uint(sKV[n0 * 68 + k8 + tg]);
                bf[nf][1] = __float_as_uint(sKV[n0 * 68 + k8 + tg + 4]);
            }
            #pragma unroll
            for (int mf = 0; mf < 2; mf++)
                #pragma unroll
                for (int nf = 0; nf < 2; nf++)
                    mma8(acc[mf][nf], a[mf][0], a[mf][1], a[mf][2], a[mf][3],
                         bf[nf][0], bf[nf][1]);
        }

        // scale + mask -> sP (fp32)
        #pragma unroll
        for (int mf = 0; mf < 2; mf++) {
            int rloc = wm * 32 + mf * 16 + g;
            #pragma unroll
            for (int nf = 0; nf < 2; nf++) {
                int kk = n0base + wn * 16 + nf * 8 + tg * 2;
                float p0 = 10000.0f * (1.0f - (float)mask[b * SQ + kk]);
                float p1 = 10000.0f * (1.0f - (float)mask[b * SQ + kk + 1]);
                sP[rloc * PSTR + kk]           = acc[mf][nf][0] * 0.125f - p0;
                sP[rloc * PSTR + kk + 1]       = acc[mf][nf][1] * 0.125f - p1;
                sP[(rloc + 8) * PSTR + kk]     = acc[mf][nf][2] * 0.125f - p0;
                sP[(rloc + 8) * PSTR + kk + 1] = acc[mf][nf][3] * 0.125f - p1;
            }
        }
    }
    __syncthreads();

    // ---- softmax over 256 cols, warp per row; store tf32 probs ----
    for (int rr = 0; rr < 8; rr++) {
        int row = warp * 8 + rr;
        float* p = &sP[row * PSTR + lane * 8];
        float v[8];
        *(float4*)&v[0] = *(float4*)p;
        *(float4*)&v[4] = *(float4*)(p + 4);

        float mx = v[0];
        #pragma unroll
        for (int j = 1; j < 8; j++) mx = fmaxf(mx, v[j]);
        #pragma unroll
        for (int o = 16; o; o >>= 1) mx = fmaxf(mx, __shfl_xor_sync(0xffffffffu, mx, o));

        float s = 0.0f;
        #pragma unroll
        for (int j = 0; j < 8; j++) { v[j] = expf(v[j] - mx); s += v[j]; }
        #pragma unroll
        for (int o = 16; o; o >>= 1) s += __shfl_xor_sync(0xffffffffu, s, o);

        float inv = 1.0f / s;
        #pragma unroll
        for (int j = 0; j < 8; j++) v[j] = to_tf32(v[j] * inv);

        *(float4*)p = *(float4*)&v[0];
        *(float4*)(p + 4) = *(float4*)&v[4];
    }
    __syncthreads();

    // ---- PV: m=64(q), n=64(dh), k=256 in 32-chunks, V double-buffered ----
    float acc2[2][2][4] = {};
    float4 vr[2];

    #pragma unroll
    for (int j = 0; j < 2; j++) {
        int f = tid + 256 * j;
        int r = f >> 4, c4 = (f & 15) << 2;
        vr[j] = *(const float4*)&Vp[(size_t)r * DH + c4];
    }
    #pragma unroll
    for (int j = 0; j < 2; j++) {
        int f = tid + 256 * j;
        int r = f >> 4, c4 = (f & 15) << 2;
        float* p = &sKV[r * 72 + c4];
        p[0] = to_tf32(vr[j].x); p[1] = to_tf32(vr[j].y);
        p[2] = to_tf32(vr[j].z); p[3] = to_tf32(vr[j].w);
    }
    __syncthreads();

    for (int c = 0; c < 8; c++) {
        const int buf = c & 1;
        const bool more = (c < 7);
        if (more) {
            #pragma unroll
            for (int j = 0; j < 2; j++) {
                int f = tid + 256 * j;
                int r = f >> 4, c4 = (f & 15) << 2;
                vr[j] = *(const float4*)&Vp[(size_t)((c + 1) * 32 + r) * DH + c4];
            }
        }

        const float* cV = &sKV[buf * 32 * 72];
        const int kbase = c * 32;
        #pragma unroll
        for (int ks = 0; ks < 4; ks++) {
            const int k8 = ks * 8;
            uint32_t a[2][4], bf[2][2];
            #pragma unroll
            for (int mf = 0; mf < 2; mf++) {
                int m0 = wm * 32 + mf * 16 + g;
                a[mf][0] = __float_as_uint(sP[m0 * PSTR + kbase + k8 + tg]);
                a[mf][1] = __float_as_uint(sP[(m0 + 8) * PSTR + kbase + k8 + tg]);
                a[mf][2] = __float_as_uint(sP[m0 * PSTR + kbase + k8 + tg + 4]);
                a[mf][3] = __float_as_uint(sP[(m0 + 8) * PSTR + kbase + k8 + tg + 4]);
            }
            #pragma unroll
            for (int nf = 0; nf < 2; nf++) {
                int n0 = wn * 16 + nf * 8 + g;
                bf[nf][0] = __float_as_uint(cV[(k8 + tg) * 72 + n0]);
                bf[nf][1] = __float_as_uint(cV[(k8 + tg + 4) * 72 + n0]);
            }
            #pragma unroll
            for (int mf = 0; mf < 2; mf++)
                #pragma unroll
                for (int nf = 0; nf < 2; nf++)
                    mma8(acc2[mf][nf], a[mf][0], a[mf][1], a[mf][2], a[mf][3],
                         bf[nf][0], bf[nf][1]);
        }

        if (more) {
            float* p0 = &sKV[(buf ^ 1) * 32 * 72];
            #pragma unroll
            for (int j = 0; j < 2; j++) {
                int f = tid + 256 * j;
                int r = f >> 4, c4 = (f & 15) << 2;
                float* p = &p0[r * 72 + c4];
                p[0] = to_tf32(vr[j].x); p[1] = to_tf32(vr[j].y);
                p[2] = to_tf32(vr[j].z); p[3] = to_tf32(vr[j].w);
            }
            __syncthreads();
        }
    }

    // ---- epilogue: out[b][q0+m][hh*64+dh] ----
    #pragma unroll
    for (int mf = 0; mf < 2; mf++) {
        int s = q0 + wm * 32 + mf * 16 + g;
        #pragma unroll
        for (int nf = 0; nf < 2; nf++) {
            int cc = hh * DH + wn * 16 + nf * 8 + tg * 2;
            *(float2*)&out[((size_t)b * SQ + s) * D + cc] =
                make_float2(acc2[mf][nf][0], acc2[mf][nf][1]);
            *(float2*)&out[((size_t)b * SQ + s + 8) * D + cc] =
                make_float2(acc2[mf][nf][2], acc2[mf][nf][3]);
        }
    }
}

// ---------------- residual add + LayerNorm (in-place on x) ----------------
__global__ __launch_bounds__(256) void addln_kernel(
    float* __restrict__ x, const float* __restrict__ hbuf,
    const float* __restrict__ g, const float* __restrict__ bta)
{
    __shared__ float red[256];
    const int row = blockIdx.x;
    const size_t base = (size_t)row * D;
    const int t = threadIdx.x;

    float v0 = x[base + t]       + hbuf[base + t];
    float v1 = x[base + t + 256] + hbuf[base + t + 256];
    float v2 = x[base + t + 512] + hbuf[base + t + 512];

    red[t] = v0 + v1 + v2;
    __syncthreads();
    for (int o = 128; o; o >>= 1) { if (t < o) red[t] += red[t + o]; __syncthreads(); }
    float mean = red[0] * (1.0f / 768.0f);
    __syncthreads();

    float d0 = v0 - mean, d1 = v1 - mean, d2 = v2 - mean;
    red[t] = d0 * d0 + d1 * d1 + d2 * d2;
    __syncthreads();
    for (int o = 128; o; o >>= 1) { if (t < o) red[t] += red[t + o]; __syncthreads(); }
    float inv = rsqrtf(red[0] * (1.0f / 768.0f) + 1e-12f);

    x[base + t]       = d0 * inv * g[t]       + bta[t];
    x[base + t + 256] = d1 * inv * g[t + 256] + bta[t + 256];
    x[base + t + 512] = d2 * inv * g[t + 512] + bta[t + 512];
}

// ---------------- host orchestration ----------------
static float *gx, *gy, *gqkv, *gh, *gffn;
static bool g_resolved = false;

#define SMEM128 ((2*128*36 + 2*32*136) * (int)sizeof(float))  // 71680
#define SMEM64  ((2*128*36 + 2*32*72)  * (int)sizeof(float))  // 55296

static void resolve_symbols() {
    if (g_resolved) return;
    cudaGetSymbolAddress((void**)&gx,   g_x);
    cudaGetSymbolAddress((void**)&gy,   g_y);
    cudaGetSymbolAddress((void**)&gqkv, g_qkv);
    cudaGetSymbolAddress((void**)&gh,   g_h);
    cudaGetSymbolAddress((void**)&gffn, g_ffn);
    cudaFuncSetAttribute(gemm_db<128,2>, cudaFuncAttributeMaxDynamicSharedMemorySize, SMEM128);
    cudaFuncSetAttribute(gemm_db<128,1>, cudaFuncAttributeMaxDynamicSharedMemorySize, SMEM128);
    cudaFuncSetAttribute(gemm_db<64,0>,  cudaFuncAttributeMaxDynamicSharedMemorySize, SMEM64);
    cudaFuncSetAttribute(attn_fused,     cudaFuncAttributeMaxDynamicSharedMemorySize, ATT_SMEM);
    g_resolved = true;
}

static void run_mhsa(const float* qin, const float* kvin,
                     const float* Wp, const float* bp, const int* mask,
                     float* stream_buf, const float* lng, const float* lnb)
{
    gemm_db<128,2><<<dim3(18, 16), 256, SMEM128>>>(qin, kvin, Wp, bp, gqkv, D, D);
    attn_fused<<<dim3(BB * H, SQ / 64), 256, ATT_SMEM>>>(gqkv, mask, gh);
    addln_kernel<<<M, 256>>>(stream_buf, gh, lng, lnb);
}

static void run_ffn(float* buf, const float* w1, const float* b1,
                    const float* w2, const float* b2,
                    const float* lng, const float* lnb)
{
    gemm_db<128,1><<<dim3(FF / 128, 16), 256, SMEM128>>>(buf, buf, w1, b1, gffn, FF, D);
    gemm_db<64,0><<<dim3(D / 64, 16), 256, SMEM64>>>(gffn, gffn, w2, b2, gh, D, FF);
    addln_kernel<<<M, 256>>>(buf, gh, lng, lnb);
}

extern "C" void kernel_launch(void* const* d_in, const int* in_sizes, int n_in,
                              void* d_out, int out_size)
{
    const float* x     = (const float*)d_in[0];
    const float* y     = (const float*)d_in[1];
    const int*   xmask = (const int*)  d_in[2];
    const int*   ymask = (const int*)  d_in[3];
    const float* ax_w  = (const float*)d_in[4];
    const float* ax_b  = (const float*)d_in[5];
    const float* cx_w  = (const float*)d_in[6];
    const float* cx_b  = (const float*)d_in[7];
    const float* fx_w1 = (const float*)d_in[8];
    const float* fx_b1 = (const float*)d_in[9];
    const float* fx_w2 = (const float*)d_in[10];
    const float* fx_b2 = (const float*)d_in[11];
    const float* ay_w  = (const float*)d_in[12];
    const float* ay_b  = (const float*)d_in[13];
    const float* cy_w  = (const float*)d_in[14];
    const float* cy_b  = (const float*)d_in[15];
    const float* fy_w1 = (const float*)d_in[16];
    const float* fy_b1 = (const float*)d_in[17];
    const float* fy_w2 = (const float*)d_in[18];
    const float* fy_b2 = (const float*)d_in[19];
    const float* lnx_g = (const float*)d_in[20];
    const float* lnx_b = (const float*)d_in[21];
    const float* lny_g = (const float*)d_in[22];
    const float* lny_b = (const float*)d_in[23];

    resolve_symbols();

    cudaMemcpyAsync(gx, x, MD * sizeof(float), cudaMemcpyDeviceToDevice, 0);
    cudaMemcpyAsync(gy, y, MD * sizeof(float), cudaMemcpyDeviceToDevice, 0);

    for (int l = 0; l < 6; l++) {
        const float* axw = ax_w + (size_t)l * 3 * D * D;
        const float* axb = ax_b + (size_t)l * 3 * D;
        const float* ayw = ay_w + (size_t)l * 3 * D * D;
        const float* ayb = ay_b + (size_t)l * 3 * D;
        const float* cxw = cx_w + (size_t)l * 3 * D * D;
        const float* cxb = cx_b + (size_t)l * 3 * D;
        const float* cyw = cy_w + (size_t)l * 3 * D * D;
        const float* cyb = cy_b + (size_t)l * 3 * D;
        const float* fxw1 = fx_w1 + (size_t)l * D * FF;
        const float* fxb1 = fx_b1 + (size_t)l * FF;
        const float* fxw2 = fx_w2 + (size_t)l * FF * D;
        const float* fxb2 = fx_b2 + (size_t)l * D;
        const float* fyw1 = fy_w1 + (size_t)l * D * FF;
        const float* fyb1 = fy_b1 + (size_t)l * FF;
        const float* fyw2 = fy_w2 + (size_t)l * FF * D;
        const float* fyb2 = fy_b2 + (size_t)l * D;

        run_mhsa(gx, gx, axw, axb, xmask, gx, lnx_g + 0 * D, lnx_b + 0 * D);
        run_mhsa(gy, gy, ayw, ayb, ymask, gy, lny_g + 0 * D, lny_b + 0 * D);
        run_mhsa(gx, gy, cxw, cxb, ymask, gx, lnx_g + 1 * D, lnx_b + 1 * D);
        run_mhsa(gy, gx, cyw, cyb, xmask, gy, lny_g + 1 * D, lny_b + 1 * D);
        run_ffn(gx, fxw1, fxb1, fxw2, fxb2, lnx_g + 2 * D, lnx_b + 2 * D);
        run_ffn(gy, fyw1, fyb1, fyw2, fyb2, lny_g + 2 * D, lny_b + 2 * D);
    }

    cudaMemcpyAsync((float*)d_out,      gx, MD * sizeof(float), cudaMemcpyDeviceToDevice, 0);
    cudaMemcpyAsync((float*)d_out + MD, gy, MD * sizeof(float), cudaMemcpyDeviceToDevice, 0);
}

// round 10
// speedup vs baseline: 1.1131x; 1.1131x over previous
#include <cuda_runtime.h>
#include <math.h>
#include <stdint.h>

// Problem dims
#define D   768
#define H   12
#define SQ  256
#define BB  8
#define DH  64
#define M   (BB*SQ)     // 2048 rows
#define FF  (4*D)       // 3072
#define MD  ((size_t)M*D)

#define WA_N  (6*3*D*D)    // 10616832 per a/c tensor
#define WF_N  (6*D*FF)     // 14155776 per w1/w2 tensor

// ---------------- scratch (device globals; no allocs allowed) ----------------
__device__ float g_x[M*D];       // fp32 stream state
__device__ float g_y[M*D];
__device__ float g_xt[M*D];      // tf32-rounded copy (GEMM A operand)
__device__ float g_yt[M*D];
__device__ float g_qkv[3*M*D];   // [3][B,H,S,DH]  (tf32-rounded)
__device__ float g_h[M*D];       // attn/ffn2 output (fp32)
__device__ float g_ffn[(size_t)M*FF]; // ffn hidden (tf32-rounded)

// pre-converted (tf32-rounded) weights
__device__ float g_axwt[WA_N];
__device__ float g_cxwt[WA_N];
__device__ float g_aywt[WA_N];
__device__ float g_cywt[WA_N];
__device__ float g_fxw1t[WF_N];
__device__ float g_fyw1t[WF_N];
__device__ float g_fxw2t[WF_N];
__device__ float g_fyw2t[WF_N];

// ---------------- tf32 helpers ----------------
__device__ __forceinline__ float to_tf32(float x) {
    float r;
    asm("cvt.rna.tf32.f32 %0, %1;" : "=f"(r) : "f"(x));
    return r;
}

__device__ __forceinline__ void mma8(float c[4],
    uint32_t a0, uint32_t a1, uint32_t a2, uint32_t a3,
    uint32_t b0, uint32_t b1)
{
    asm volatile(
        "mma.sync.aligned.m16n8k8.row.col.f32.tf32.tf32.f32 "
        "{%0,%1,%2,%3}, {%4,%5,%6,%7}, {%8,%9}, {%0,%1,%2,%3};"
        : "+f"(c[0]), "+f"(c[1]), "+f"(c[2]), "+f"(c[3])
        : "r"(a0), "r"(a1), "r"(a2), "r"(a3), "r"(b0), "r"(b1));
}

__device__ __forceinline__ float gelu_exact(float v) {
    return 0.5f * v * (1.0f + erff(v * 0.70710678118654752f));
}

#define CP16(dst, src) \
    asm volatile("cp.async.cg.shared.global [%0], [%1], 16;\n" :: "r"(dst), "l"(src))
#define CP_COMMIT() asm volatile("cp.async.commit_group;\n" ::: "memory")
#define CP_WAIT1()  asm volatile("cp.async.wait_group 1;\n" ::: "memory")

// ---------------- conversion kernels ----------------
__global__ void cvt4_kernel(const float4* __restrict__ in, float4* __restrict__ out, int n4)
{
    int i = blockIdx.x * 256 + threadIdx.x;
    if (i < n4) {
        float4 v = in[i];
        v.x = to_tf32(v.x); v.y = to_tf32(v.y);
        v.z = to_tf32(v.z); v.w = to_tf32(v.w);
        out[i] = v;
    }
}

__global__ void copycvt4_kernel(const float4* __restrict__ in,
                                float4* __restrict__ outf, float4* __restrict__ outt, int n4)
{
    int i = blockIdx.x * 256 + threadIdx.x;
    if (i < n4) {
        float4 v = in[i];
        outf[i] = v;
        v.x = to_tf32(v.x); v.y = to_tf32(v.y);
        v.z = to_tf32(v.z); v.w = to_tf32(v.w);
        outt[i] = v;
    }
}

// ============================================================================
// 3-stage cp.async tf32 GEMM.  Block tile 128 x BN, BK=32, 256 threads,
// 8 warps as 2(m) x 4(n): warp tile 64 x (BN/4).
// All operands MUST be pre-rounded to tf32 (mma truncation is then exact).
// MODE: 0 = plain+bias (fp32 out), 1 = bias+GELU (tf32 out),
//       2 = QKV fused (tf32 out, scatter to [mat][B,H,S,DH], N==768).
// ============================================================================
template<int BN, int MODE>
__global__ __launch_bounds__(256) void gemm_ca(
    const float* __restrict__ Aq, const float* __restrict__ Akv,
    const float* __restrict__ W, const float* __restrict__ bias,
    float* __restrict__ C, int N, int K)
{
    constexpr int BP = BN + 8;
    constexpr int NF = BN / 32;
    constexpr int WN = BN / 4;
    constexpr int NB4 = BN / 32;          // B float4 loads per thread
    constexpr int ASZ = 128 * 36;
    constexpr int BSZ = 32 * BP;

    extern __shared__ float smem[];
    float* sA = smem;            // [3][128][36]
    float* sB = smem + 3 * ASZ;  // [3][32][BP]

    const int tid = threadIdx.x;
    const int lane = tid & 31, warp = tid >> 5;
    const int wm = warp >> 2, wn = warp & 3;
    const int g = lane >> 2, tg = lane & 3;
    const int row0 = blockIdx.y * 128;

    const float* A; const float* Wp; const float* bp; float* Cp; int col0;
    if (MODE == 2) {
        const int perMat = 768 / BN;
        const int mat = blockIdx.x / perMat;
        col0 = (blockIdx.x % perMat) * BN;
        A  = (mat == 0) ? Aq : Akv;
        Wp = W + (size_t)mat * D * D;
        bp = bias + mat * D;
        Cp = C + (size_t)mat * MD;
    } else {
        col0 = blockIdx.x * BN;
        A = Aq; Wp = W; bp = bias; Cp = C;
    }

    const uint32_t sAu = (uint32_t)__cvta_generic_to_shared(sA);
    const uint32_t sBu = (uint32_t)__cvta_generic_to_shared(sB);

    float acc[4][NF][4] = {};

    #define ISSUE(ST, K0) { \
        _Pragma("unroll") \
        for (int j = 0; j < 4; j++) { \
            int f = tid + 256 * j; \
            int r = f >> 3, c4 = (f & 7) << 2; \
            uint32_t dst = sAu + (uint32_t)(((ST) * ASZ + r * 36 + c4) * 4); \
            CP16(dst, &A[(size_t)(row0 + r) * K + (K0) + c4]); \
        } \
        _Pragma("unroll") \
        for (int j = 0; j < NB4; j++) { \
            int f = tid + 256 * j; \
            int r = f / (BN / 4), c4 = (f % (BN / 4)) << 2; \
            uint32_t dst = sBu + (uint32_t)(((ST) * BSZ + r * BP + c4) * 4); \
            CP16(dst, &Wp[(size_t)((K0) + r) * N + col0 + c4]); \
        } }

    ISSUE(0, 0);
    CP_COMMIT();
    ISSUE(1, 32);
    CP_COMMIT();

    const int kt = K >> 5;
    for (int i = 0; i < kt; i++) {
        CP_WAIT1();
        __syncthreads();

        const float* cA = &sA[(i % 3) * ASZ];
        const float* cB = &sB[(i % 3) * BSZ];
        #pragma unroll
        for (int ks = 0; ks < 4; ks++) {
            const int k8 = ks * 8;
            uint32_t a[4][4], b[NF][2];
            #pragma unroll
            for (int mf = 0; mf < 4; mf++) {
                int m0 = wm * 64 + mf * 16 + g;
                a[mf][0] = __float_as_uint(cA[m0 * 36 + k8 + tg]);
                a[mf][1] = __float_as_uint(cA[(m0 + 8) * 36 + k8 + tg]);
                a[mf][2] = __float_as_uint(cA[m0 * 36 + k8 + tg + 4]);
                a[mf][3] = __float_as_uint(cA[(m0 + 8) * 36 + k8 + tg + 4]);
            }
            #pragma unroll
            for (int nf = 0; nf < NF; nf++) {
                int n0 = wn * WN + nf * 8 + g;
                b[nf][0] = __float_as_uint(cB[(k8 + tg) * BP + n0]);
                b[nf][1] = __float_as_uint(cB[(k8 + tg + 4) * BP + n0]);
            }
            #pragma unroll
            for (int mf = 0; mf < 4; mf++)
                #pragma unroll
                for (int nf = 0; nf < NF; nf++)
                    mma8(acc[mf][nf], a[mf][0], a[mf][1], a[mf][2], a[mf][3],
                         b[nf][0], b[nf][1]);
        }

        const int nk = i + 2;
        if (nk < kt) ISSUE(nk % 3, nk << 5);
        CP_COMMIT();
    }

    #undef ISSUE

    // ---- epilogue ----
    #pragma unroll
    for (int mf = 0; mf < 4; mf++) {
        int r_lo = row0 + wm * 64 + mf * 16 + g;
        #pragma unroll
        for (int nf = 0; nf < NF; nf++) {
            int c = col0 + wn * WN + nf * 8 + tg * 2;
            float b0 = bp[c], b1 = bp[c + 1];
            float v00 = acc[mf][nf][0] + b0, v01 = acc[mf][nf][1] + b1;
            float v10 = acc[mf][nf][2] + b0, v11 = acc[mf][nf][3] + b1;
            if (MODE == 1) {
                v00 = to_tf32(gelu_exact(v00)); v01 = to_tf32(gelu_exact(v01));
                v10 = to_tf32(gelu_exact(v10)); v11 = to_tf32(gelu_exact(v11));
            }
            if (MODE == 2) {
                v00 = to_tf32(v00); v01 = to_tf32(v01);
                v10 = to_tf32(v10); v11 = to_tf32(v11);
                int hh = c >> 6, dh = c & 63;
                int b_0 = r_lo >> 8, s_0 = r_lo & 255;
                int b_1 = (r_lo + 8) >> 8, s_1 = (r_lo + 8) & 255;
                *(float2*)&Cp[(((size_t)b_0 * H + hh) * SQ + s_0) * DH + dh] = make_float2(v00, v01);
                *(float2*)&Cp[(((size_t)b_1 * H + hh) * SQ + s_1) * DH + dh] = make_float2(v10, v11);
            } else {
                *(float2*)&Cp[(size_t)r_lo * N + c] = make_float2(v00, v01);
                *(float2*)&Cp[(size_t)(r_lo + 8) * N + c] = make_float2(v10, v11);
            }
        }
    }
}

// ============================================================================
// Fused attention: scores (QK^T * 0.125 + mask) -> softmax -> P @ V -> out.
// QKV inputs are pre-rounded tf32 (no cvt on load).
// ============================================================================
#define PSTR 260
#define KVREG 4608
#define ATT_SMEM ((64*68 + 64*PSTR + KVREG) * (int)sizeof(float))

__global__ __launch_bounds__(256) void attn_fused(
    const float* __restrict__ QKV,   // [3][B,H,S,DH]
    const int* __restrict__ mask,    // [B,S]
    float* __restrict__ out)         // [B,S,D]
{
    extern __shared__ float smem[];
    float* sQ = smem;                 // [64][68]
    float* sP = smem + 64 * 68;       // [64][260]
    float* sKV = sP + 64 * PSTR;      // [64][68] (scores) / 2x[32][72] (PV)

    const int tid = threadIdx.x;
    const int lane = tid & 31, warp = tid >> 5;
    const int wm = warp >> 2, wn = warp & 3;
    const int g = lane >> 2, tg = lane & 3;

    const int bh = blockIdx.x;
    const int b = bh / H, hh = bh % H;
    const int q0 = blockIdx.y * 64;

    const float* Qp = QKV + ((size_t)bh * SQ + q0) * DH;
    const float* Kp = QKV + MD + (size_t)bh * SQ * DH;
    const float* Vp = QKV + 2 * MD + (size_t)bh * SQ * DH;

    #pragma unroll
    for (int j = 0; j < 4; j++) {
        int f = tid + 256 * j;
        int r = f >> 4, c4 = (f & 15) << 2;
        *(float4*)&sQ[r * 68 + c4] = *(const float4*)&Qp[(size_t)r * DH + c4];
    }

    for (int stage = 0; stage < 4; stage++) {
        const int n0base = stage * 64;
        __syncthreads();
        #pragma unroll
        for (int j = 0; j < 4; j++) {
            int f = tid + 256 * j;
            int r = f >> 4, c4 = (f & 15) << 2;
            *(float4*)&sKV[r * 68 + c4] = *(const float4*)&Kp[(size_t)(n0base + r) * DH + c4];
        }
        __syncthreads();

        float acc[2][2][4] = {};
        #pragma unroll
        for (int ks = 0; ks < 8; ks++) {
            const int k8 = ks * 8;
            uint32_t a[2][4], bf[2][2];
            #pragma unroll
            for (int mf = 0; mf < 2; mf++) {
                int m0 = wm * 32 + mf * 16 + g;
                a[mf][0] = __float_as_uint(sQ[m0 * 68 + k8 + tg]);
                a[mf][1] = __float_as_uint(sQ[(m0 + 8) * 68 + k8 + tg]);
                a[mf][2] = __float_as_uint(sQ[m0 * 68 + k8 + tg + 4]);
                a[mf][3] = __float_as_uint(sQ[(m0 + 8) * 68 + k8 + tg + 4]);
            }
            #pragma unroll
            for (int nf = 0; nf < 2; nf++) {
                int n0 = wn * 16 + nf * 8 + g;
                bf[nf][0] = __float_as_uint(sKV[n0 * 68 + k8 + tg]);
                bf[nf][1] = __float_as_uint(sKV[n0 * 68 + k8 + tg + 4]);
            }
            #pragma unroll
            for (int mf = 0; mf < 2; mf++)
                #pragma unroll
                for (int nf = 0; nf < 2; nf++)
                    mma8(acc[mf][nf], a[mf][0], a[mf][1], a[mf][2], a[mf][3],
                         bf[nf][0], bf[nf][1]);
        }

        #pragma unroll
        for (int mf = 0; mf < 2; mf++) {
            int rloc = wm * 32 + mf * 16 + g;
            #pragma unroll
            for (int nf = 0; nf < 2; nf++) {
                int kk = n0base + wn * 16 + nf * 8 + tg * 2;
                float p0 = 10000.0f * (1.0f - (float)mask[b * SQ + kk]);
                float p1 = 10000.0f * (1.0f - (float)mask[b * SQ + kk + 1]);
                sP[rloc * PSTR + kk]           = acc[mf][nf][0] * 0.125f - p0;
                sP[rloc * PSTR + kk + 1]       = acc[mf][nf][1] * 0.125f - p1;
                sP[(rloc + 8) * PSTR + kk]     = acc[mf][nf][2] * 0.125f - p0;
                sP[(rloc + 8) * PSTR + kk + 1] = acc[mf][nf][3] * 0.125f - p1;
            }
        }
    }
    __syncthreads();

    // softmax (fp32, then round probs to tf32)
    for (int rr = 0; rr < 8; rr++) {
        int row = warp * 8 + rr;
        float* p = &sP[row * PSTR + lane * 8];
        float v[8];
        *(float4*)&v[0] = *(float4*)p;
        *(float4*)&v[4] = *(float4*)(p + 4);

        float mx = v[0];
        #pragma unroll
        for (int j = 1; j < 8; j++) mx = fmaxf(mx, v[j]);
        #pragma unroll
        for (int o = 16; o; o >>= 1) mx = fmaxf(mx, __shfl_xor_sync(0xffffffffu, mx, o));

        float s = 0.0f;
        #pragma unroll
        for (int j = 0; j < 8; j++) { v[j] = expf(v[j] - mx); s += v[j]; }
        #pragma unroll
        for (int o = 16; o; o >>= 1) s += __shfl_xor_sync(0xffffffffu, s, o);

        float inv = 1.0f / s;
        #pragma unroll
        for (int j = 0; j < 8; j++) v[j] = to_tf32(v[j] * inv);

        *(float4*)p = *(float4*)&v[0];
        *(float4*)(p + 4) = *(float4*)&v[4];
    }
    __syncthreads();

    // PV
    float acc2[2][2][4] = {};
    #pragma unroll
    for (int j = 0; j < 2; j++) {
        int f = tid + 256 * j;
        int r = f >> 4, c4 = (f & 15) << 2;
        *(float4*)&sKV[r * 72 + c4] = *(const float4*)&Vp[(size_t)r * DH + c4];
    }
    __syncthreads();

    for (int c = 0; c < 8; c++) {
        const int buf = c & 1;
        const bool more = (c < 7);
        float4 vr[2];
        if (more) {
            #pragma unroll
            for (int j = 0; j < 2; j++) {
                int f = tid + 256 * j;
                int r = f >> 4, c4 = (f & 15) << 2;
                vr[j] = *(const float4*)&Vp[(size_t)((c + 1) * 32 + r) * DH + c4];
            }
        }

        const float* cV = &sKV[buf * 32 * 72];
        const int kbase = c * 32;
        #pragma unroll
        for (int ks = 0; ks < 4; ks++) {
            const int k8 = ks * 8;
            uint32_t a[2][4], bf[2][2];
            #pragma unroll
            for (int mf = 0; mf < 2; mf++) {
                int m0 = wm * 32 + mf * 16 + g;
                a[mf][0] = __float_as_uint(sP[m0 * PSTR + kbase + k8 + tg]);
                a[mf][1] = __float_as_uint(sP[(m0 + 8) * PSTR + kbase + k8 + tg]);
                a[mf][2] = __float_as_uint(sP[m0 * PSTR + kbase + k8 + tg + 4]);
                a[mf][3] = __float_as_uint(sP[(m0 + 8) * PSTR + kbase + k8 + tg + 4]);
            }
            #pragma unroll
            for (int nf = 0; nf < 2; nf++) {
                int n0 = wn * 16 + nf * 8 + g;
                bf[nf][0] = __float_as_uint(cV[(k8 + tg) * 72 + n0]);
                bf[nf][1] = __float_as_uint(cV[(k8 + tg + 4) * 72 + n0]);
            }
            #pragma unroll
            for (int mf = 0; mf < 2; mf++)
                #pragma unroll
                for (int nf = 0; nf < 2; nf++)
                    mma8(acc2[mf][nf], a[mf][0], a[mf][1], a[mf][2], a[mf][3],
                         bf[nf][0], bf[nf][1]);
        }

        if (more) {
            float* p0 = &sKV[(buf ^ 1) * 32 * 72];
            #pragma unroll
            for (int j = 0; j < 2; j++) {
                int f = tid + 256 * j;
                int r = f >> 4, c4 = (f & 15) << 2;
                *(float4*)&p0[r * 72 + c4] = vr[j];
            }
            __syncthreads();
        }
    }

    #pragma unroll
    for (int mf = 0; mf < 2; mf++) {
        int s = q0 + wm * 32 + mf * 16 + g;
        #pragma unroll
        for (int nf = 0; nf < 2; nf++) {
            int cc = hh * DH + wn * 16 + nf * 8 + tg * 2;
            *(float2*)&out[((size_t)b * SQ + s) * D + cc] =
                make_float2(acc2[mf][nf][0], acc2[mf][nf][1]);
            *(float2*)&out[((size_t)b * SQ + s + 8) * D + cc] =
                make_float2(acc2[mf][nf][2], acc2[mf][nf][3]);
        }
    }
}

// ---------------- residual add + LayerNorm (fp32 state + tf32 copy) ----------------
__global__ __launch_bounds__(256) void addln_kernel(
    float* __restrict__ x, const float* __restrict__ hbuf,
    const float* __restrict__ g, const float* __restrict__ bta,
    float* __restrict__ xt)
{
    __shared__ float red[256];
    const int row = blockIdx.x;
    const size_t base = (size_t)row * D;
    const int t = threadIdx.x;

    float v0 = x[base + t]       + hbuf[base + t];
    float v1 = x[base + t + 256] + hbuf[base + t + 256];
    float v2 = x[base + t + 512] + hbuf[base + t + 512];

    red[t] = v0 + v1 + v2;
    __syncthreads();
    for (int o = 128; o; o >>= 1) { if (t < o) red[t] += red[t + o]; __syncthreads(); }
    float mean = red[0] * (1.0f / 768.0f);
    __syncthreads();

    float d0 = v0 - mean, d1 = v1 - mean, d2 = v2 - mean;
    red[t] = d0 * d0 + d1 * d1 + d2 * d2;
    __syncthreads();
    for (int o = 128; o; o >>= 1) { if (t < o) red[t] += red[t + o]; __syncthreads(); }
    float inv = rsqrtf(red[0] * (1.0f / 768.0f) + 1e-12f);

    float r0 = d0 * inv * g[t]       + bta[t];
    float r1 = d1 * inv * g[t + 256] + bta[t + 256];
    float r2 = d2 * inv * g[t + 512] + bta[t + 512];
    x[base + t]        = r0;
    x[base + t + 256]  = r1;
    x[base + t + 512]  = r2;
    xt[base + t]       = to_tf32(r0);
    xt[base + t + 256] = to_tf32(r1);
    xt[base + t + 512] = to_tf32(r2);
}

// ---------------- host orchestration ----------------
static float *gx, *gy, *gxt, *gyt, *gqkv, *gh, *gffn;
static float *waxt, *wcxt, *wayt, *wcyt, *wfx1, *wfy1, *wfx2, *wfy2;
static bool g_resolved = false;

#define SMEM_CA128 (3*(128*36 + 32*136) * (int)sizeof(float))  // 107520
#define SMEM_CA64  (3*(128*36 + 32*72)  * (int)sizeof(float))  // 82944

static void resolve_symbols() {
    if (g_resolved) return;
    cudaGetSymbolAddress((void**)&gx,   g_x);
    cudaGetSymbolAddress((void**)&gy,   g_y);
    cudaGetSymbolAddress((void**)&gxt,  g_xt);
    cudaGetSymbolAddress((void**)&gyt,  g_yt);
    cudaGetSymbolAddress((void**)&gqkv, g_qkv);
    cudaGetSymbolAddress((void**)&gh,   g_h);
    cudaGetSymbolAddress((void**)&gffn, g_ffn);
    cudaGetSymbolAddress((void**)&waxt, g_axwt);
    cudaGetSymbolAddress((void**)&wcxt, g_cxwt);
    cudaGetSymbolAddress((void**)&wayt, g_aywt);
    cudaGetSymbolAddress((void**)&wcyt, g_cywt);
    cudaGetSymbolAddress((void**)&wfx1, g_fxw1t);
    cudaGetSymbolAddress((void**)&wfy1, g_fyw1t);
    cudaGetSymbolAddress((void**)&wfx2, g_fxw2t);
    cudaGetSymbolAddress((void**)&wfy2, g_fyw2t);
    cudaFuncSetAttribute(gemm_ca<128,2>, cudaFuncAttributeMaxDynamicSharedMemorySize, SMEM_CA128);
    cudaFuncSetAttribute(gemm_ca<128,1>, cudaFuncAttributeMaxDynamicSharedMemorySize, SMEM_CA128);
    cudaFuncSetAttribute(gemm_ca<64,0>,  cudaFuncAttributeMaxDynamicSharedMemorySize, SMEM_CA64);
    cudaFuncSetAttribute(attn_fused,     cudaFuncAttributeMaxDynamicSharedMemorySize, ATT_SMEM);
    g_resolved = true;
}

static void run_mhsa(const float* qin_t, const float* kvin_t,
                     const float* Wt, const float* bp, const int* mask,
                     float* x_state, float* x_t,
                     const float* lng, const float* lnb)
{
    gemm_ca<128,2><<<dim3(18, 16), 256, SMEM_CA128>>>(qin_t, kvin_t, Wt, bp, gqkv, D, D);
    attn_fused<<<dim3(BB * H, SQ / 64), 256, ATT_SMEM>>>(gqkv, mask, gh);
    addln_kernel<<<M, 256>>>(x_state, gh, lng, lnb, x_t);
}

static void run_ffn(float* x_state, float* x_t,
                    const float* w1t, const float* b1,
                    const float* w2t, const float* b2,
                    const float* lng, const float* lnb)
{
    gemm_ca<128,1><<<dim3(FF / 128, 16), 256, SMEM_CA128>>>(x_t, x_t, w1t, b1, gffn, FF, D);
    gemm_ca<64,0><<<dim3(D / 64, 16), 256, SMEM_CA64>>>(gffn, gffn, w2t, b2, gh, D, FF);
    addln_kernel<<<M, 256>>>(x_state, gh, lng, lnb, x_t);
}

extern "C" void kernel_launch(void* const* d_in, const int* in_sizes, int n_in,
                              void* d_out, int out_size)
{
    const float* x     = (const float*)d_in[0];
    const float* y     = (const float*)d_in[1];
    const int*   xmask = (const int*)  d_in[2];
    const int*   ymask = (const int*)  d_in[3];
    const float* ax_w  = (const float*)d_in[4];
    const float* ax_b  = (const float*)d_in[5];
    const float* cx_w  = (const float*)d_in[6];
    const float* cx_b  = (const float*)d_in[7];
    const float* fx_w1 = (const float*)d_in[8];
    const float* fx_b1 = (const float*)d_in[9];
    const float* fx_w2 = (const float*)d_in[10];
    const float* fx_b2 = (const float*)d_in[11];
    const float* ay_w  = (const float*)d_in[12];
    const float* ay_b  = (const float*)d_in[13];
    const float* cy_w  = (const float*)d_in[14];
    const float* cy_b  = (const float*)d_in[15];
    const float* fy_w1 = (const float*)d_in[16];
    const float* fy_b1 = (const float*)d_in[17];
    const float* fy_w2 = (const float*)d_in[18];
    const float* fy_b2 = (const float*)d_in[19];
    const float* lnx_g = (const float*)d_in[20];
    const float* lnx_b = (const float*)d_in[21];
    const float* lny_g = (const float*)d_in[22];
    const float* lny_b = (const float*)d_in[23];

    resolve_symbols();

    // pre-round weights + stream state to tf32
    {
        const int na4 = WA_N / 4, nf4 = WF_N / 4, nx4 = (int)(MD / 4);
        cvt4_kernel<<<(na4 + 255) / 256, 256>>>((const float4*)ax_w, (float4*)waxt, na4);
        cvt4_kernel<<<(na4 + 255) / 256, 256>>>((const float4*)cx_w, (float4*)wcxt, na4);
        cvt4_kernel<<<(na4 + 255) / 256, 256>>>((const float4*)ay_w, (float4*)wayt, na4);
        cvt4_kernel<<<(na4 + 255) / 256, 256>>>((const float4*)cy_w, (float4*)wcyt, na4);
        cvt4_kernel<<<(nf4 + 255) / 256, 256>>>((const float4*)fx_w1, (float4*)wfx1, nf4);
        cvt4_kernel<<<(nf4 + 255) / 256, 256>>>((const float4*)fy_w1, (float4*)wfy1, nf4);
        cvt4_kernel<<<(nf4 + 255) / 256, 256>>>((const float4*)fx_w2, (float4*)wfx2, nf4);
        cvt4_kernel<<<(nf4 + 255) / 256, 256>>>((const float4*)fy_w2, (float4*)wfy2, nf4);
        copycvt4_kernel<<<(nx4 + 255) / 256, 256>>>((const float4*)x, (float4*)gx, (float4*)gxt, nx4);
        copycvt4_kernel<<<(nx4 + 255) / 256, 256>>>((const float4*)y, (float4*)gy, (float4*)gyt, nx4);
    }

    for (int l = 0; l < 6; l++) {
        const float* axw = waxt + (size_t)l * 3 * D * D;
        const float* axb = ax_b + (size_t)l * 3 * D;
        const float* ayw = wayt + (size_t)l * 3 * D * D;
        const float* ayb = ay_b + (size_t)l * 3 * D;
        const float* cxw = wcxt + (size_t)l * 3 * D * D;
        const float* cxb = cx_b + (size_t)l * 3 * D;
        const float* cyw = wcyt + (size_t)l * 3 * D * D;
        const float* cyb = cy_b + (size_t)l * 3 * D;
        const float* fxw1 = wfx1 + (size_t)l * D * FF;
        const float* fxb1 = fx_b1 + (size_t)l * FF;
        const float* fxw2 = wfx2 + (size_t)l * FF * D;
        const float* fxb2 = fx_b2 + (size_t)l * D;
        const float* fyw1 = wfy1 + (size_t)l * D * FF;
        const float* fyb1 = fy_b1 + (size_t)l * FF;
        const float* fyw2 = wfy2 + (size_t)l * FF * D;
        const float* fyb2 = fy_b2 + (size_t)l * D;

        run_mhsa(gxt, gxt, axw, axb, xmask, gx, gxt, lnx_g + 0 * D, lnx_b + 0 * D);
        run_mhsa(gyt, gyt, ayw, ayb, ymask, gy, gyt, lny_g + 0 * D, lny_b + 0 * D);
        run_mhsa(gxt, gyt, cxw, cxb, ymask, gx, gxt, lnx_g + 1 * D, lnx_b + 1 * D);
        run_mhsa(gyt, gxt, cyw, cyb, xmask, gy, gyt, lny_g + 1 * D, lny_b + 1 * D);
        run_ffn(gx, gxt, fxw1, fxb1, fxw2, fxb2, lnx_g + 2 * D, lnx_b + 2 * D);
        run_ffn(gy, gyt, fyw1, fyb1, fyw2, fyb2, lny_g + 2 * D, lny_b + 2 * D);
    }

    cudaMemcpyAsync((float*)d_out,      gx, MD * sizeof(float), cudaMemcpyDeviceToDevice, 0);
    cudaMemcpyAsync((float*)d_out + MD, gy, MD * sizeof(float), cudaMemcpyDeviceToDevice, 0);
}

// round 12
// speedup vs baseline: 1.2062x; 1.0836x over previous
#include <cuda_runtime.h>
#include <math.h>
#include <stdint.h>

// Problem dims
#define D   768
#define H   12
#define SQ  256
#define BB  8
#define DH  64
#define M   (BB*SQ)     // 2048 rows
#define FF  (4*D)       // 3072
#define MD  ((size_t)M*D)

#define WA_N  (6*3*D*D)
#define WF_N  (6*D*FF)

// ---------------- scratch (device globals; no allocs allowed) ----------------
__device__ float g_x[M*D];        // fp32 stream state
__device__ float g_y[M*D];
__device__ float g_xt[M*D];       // tf32-rounded copy (GEMM A operand)
__device__ float g_yt[M*D];
__device__ float g_qkv[6*M*D];    // [2 streams][3][B,H,S,DH] (tf32)
__device__ float g_h[2*M*D];      // attn/ffn2 output (fp32), per stream
__device__ float g_ffn[(size_t)2*M*FF]; // ffn hidden (tf32), per stream

// pre-converted (tf32-rounded) weights
__device__ float g_axwt[WA_N];
__device__ float g_cxwt[WA_N];
__device__ float g_aywt[WA_N];
__device__ float g_cywt[WA_N];
__device__ float g_fxw1t[WF_N];
__device__ float g_fyw1t[WF_N];
__device__ float g_fxw2t[WF_N];
__device__ float g_fyw2t[WF_N];

// ---------------- tf32 helpers ----------------
__device__ __forceinline__ float to_tf32(float x) {
    float r;
    asm("cvt.rna.tf32.f32 %0, %1;" : "=f"(r) : "f"(x));
    return r;
}

__device__ __forceinline__ void mma8(float c[4],
    uint32_t a0, uint32_t a1, uint32_t a2, uint32_t a3,
    uint32_t b0, uint32_t b1)
{
    asm volatile(
        "mma.sync.aligned.m16n8k8.row.col.f32.tf32.tf32.f32 "
        "{%0,%1,%2,%3}, {%4,%5,%6,%7}, {%8,%9}, {%0,%1,%2,%3};"
        : "+f"(c[0]), "+f"(c[1]), "+f"(c[2]), "+f"(c[3])
        : "r"(a0), "r"(a1), "r"(a2), "r"(a3), "r"(b0), "r"(b1));
}

__device__ __forceinline__ float gelu_exact(float v) {
    return 0.5f * v * (1.0f + erff(v * 0.70710678118654752f));
}

#define CP16(dst, src) \
    asm volatile("cp.async.cg.shared.global [%0], [%1], 16;\n" :: "r"(dst), "l"(src))
#define CP_COMMIT() asm volatile("cp.async.commit_group;\n" ::: "memory")
#define CP_WAIT1()  asm volatile("cp.async.wait_group 1;\n" ::: "memory")

// ---------------- conversion kernels (4 tensors per launch) ----------------
__global__ void cvt4x4_kernel(const float4* __restrict__ i0, float4* __restrict__ o0,
                              const float4* __restrict__ i1, float4* __restrict__ o1,
                              const float4* __restrict__ i2, float4* __restrict__ o2,
                              const float4* __restrict__ i3, float4* __restrict__ o3,
                              int n4)
{
    int i = blockIdx.x * 256 + threadIdx.x;
    if (i >= n4) return;
    const float4* in; float4* out;
    switch (blockIdx.y) {
        case 0: in = i0; out = o0; break;
        case 1: in = i1; out = o1; break;
        case 2: in = i2; out = o2; break;
        default: in = i3; out = o3; break;
    }
    float4 v = in[i];
    v.x = to_tf32(v.x); v.y = to_tf32(v.y);
    v.z = to_tf32(v.z); v.w = to_tf32(v.w);
    out[i] = v;
}

__global__ void copycvt4_kernel(const float4* __restrict__ i0, float4* __restrict__ f0, float4* __restrict__ t0,
                                const float4* __restrict__ i1, float4* __restrict__ f1, float4* __restrict__ t1,
                                int n4)
{
    int i = blockIdx.x * 256 + threadIdx.x;
    if (i >= n4) return;
    const float4* in; float4 *outf, *outt;
    if (blockIdx.y == 0) { in = i0; outf = f0; outt = t0; }
    else                 { in = i1; outf = f1; outt = t1; }
    float4 v = in[i];
    outf[i] = v;
    v.x = to_tf32(v.x); v.y = to_tf32(v.y);
    v.z = to_tf32(v.z); v.w = to_tf32(v.w);
    outt[i] = v;
}

// ============================================================================
// 3-stage cp.async tf32 GEMM with dual-stream axis (blockIdx.z).
// Block tile 128 x BN, BK=32, 256 threads, 8 warps 2(m) x 4(n).
// MODE: 0 = plain+bias (fp32 out), 1 = bias+GELU (tf32 out),
//       2 = QKV fused (tf32 out, scatter, N==768; A0q for mat0, A0kv mats 1,2).
// Stream s uses {A s q/kv, W s, b s} and C + s*cstride.
// ============================================================================
template<int BN, int MODE>
__global__ __launch_bounds__(256) void gemm_ca(
    const float* __restrict__ A0q, const float* __restrict__ A0kv,
    const float* __restrict__ A1q, const float* __restrict__ A1kv,
    const float* __restrict__ W0, const float* __restrict__ W1,
    const float* __restrict__ b0s, const float* __restrict__ b1s,
    float* __restrict__ C, int N, int K, size_t cstride)
{
    constexpr int BP = BN + 8;
    constexpr int NF = BN / 32;
    constexpr int WN = BN / 4;
    constexpr int NB4 = BN / 32;
    constexpr int ASZ = 128 * 36;
    constexpr int BSZ = 32 * BP;

    extern __shared__ float smem[];
    float* sA = smem;            // [3][128][36]
    float* sB = smem + 3 * ASZ;  // [3][32][BP]

    const int tid = threadIdx.x;
    const int lane = tid & 31, warp = tid >> 5;
    const int wm = warp >> 2, wn = warp & 3;
    const int g = lane >> 2, tg = lane & 3;
    const int row0 = blockIdx.y * 128;
    const int stream = blockIdx.z;

    const float* Aq  = stream ? A1q  : A0q;
    const float* Akv = stream ? A1kv : A0kv;
    const float* Wbase = stream ? W1 : W0;
    const float* bbase = stream ? b1s : b0s;
    float* Cbase = C + (size_t)stream * cstride;

    const float* A; const float* Wp; const float* bp; float* Cp; int col0;
    if (MODE == 2) {
        const int perMat = 768 / BN;
        const int mat = blockIdx.x / perMat;
        col0 = (blockIdx.x % perMat) * BN;
        A  = (mat == 0) ? Aq : Akv;
        Wp = Wbase + (size_t)mat * D * D;
        bp = bbase + mat * D;
        Cp = Cbase + (size_t)mat * MD;
    } else {
        col0 = blockIdx.x * BN;
        A = Aq; Wp = Wbase; bp = bbase; Cp = Cbase;
    }

    const uint32_t sAu = (uint32_t)__cvta_generic_to_shared(sA);
    const uint32_t sBu = (uint32_t)__cvta_generic_to_shared(sB);

    float acc[4][NF][4] = {};

    #define ISSUE(ST, K0) { \
        _Pragma("unroll") \
        for (int j = 0; j < 4; j++) { \
            int f = tid + 256 * j; \
            int r = f >> 3, c4 = (f & 7) << 2; \
            uint32_t dst = sAu + (uint32_t)(((ST) * ASZ + r * 36 + c4) * 4); \
            CP16(dst, &A[(size_t)(row0 + r) * K + (K0) + c4]); \
        } \
        _Pragma("unroll") \
        for (int j = 0; j < NB4; j++) { \
            int f = tid + 256 * j; \
            int r = f / (BN / 4), c4 = (f % (BN / 4)) << 2; \
            uint32_t dst = sBu + (uint32_t)(((ST) * BSZ + r * BP + c4) * 4); \
            CP16(dst, &Wp[(size_t)((K0) + r) * N + col0 + c4]); \
        } }

    ISSUE(0, 0);
    CP_COMMIT();
    ISSUE(1, 32);
    CP_COMMIT();

    const int kt = K >> 5;
    for (int i = 0; i < kt; i++) {
        CP_WAIT1();
        __syncthreads();

        const float* cA = &sA[(i % 3) * ASZ];
        const float* cB = &sB[(i % 3) * BSZ];
        #pragma unroll
        for (int ks = 0; ks < 4; ks++) {
            const int k8 = ks * 8;
            uint32_t a[4][4], b[NF][2];
            #pragma unroll
            for (int mf = 0; mf < 4; mf++) {
                int m0 = wm * 64 + mf * 16 + g;
                a[mf][0] = __float_as_uint(cA[m0 * 36 + k8 + tg]);
                a[mf][1] = __float_as_uint(cA[(m0 + 8) * 36 + k8 + tg]);
                a[mf][2] = __float_as_uint(cA[m0 * 36 + k8 + tg + 4]);
                a[mf][3] = __float_as_uint(cA[(m0 + 8) * 36 + k8 + tg + 4]);
            }
            #pragma unroll
            for (int nf = 0; nf < NF; nf++) {
                int n0 = wn * WN + nf * 8 + g;
                b[nf][0] = __float_as_uint(cB[(k8 + tg) * BP + n0]);
                b[nf][1] = __float_as_uint(cB[(k8 + tg + 4) * BP + n0]);
            }
            #pragma unroll
            for (int mf = 0; mf < 4; mf++)
                #pragma unroll
                for (int nf = 0; nf < NF; nf++)
                    mma8(acc[mf][nf], a[mf][0], a[mf][1], a[mf][2], a[mf][3],
                         b[nf][0], b[nf][1]);
        }

        const int nk = i + 2;
        if (nk < kt) ISSUE(nk % 3, nk << 5);
        CP_COMMIT();
    }

    #undef ISSUE

    // ---- epilogue ----
    #pragma unroll
    for (int mf = 0; mf < 4; mf++) {
        int r_lo = row0 + wm * 64 + mf * 16 + g;
        #pragma unroll
        for (int nf = 0; nf < NF; nf++) {
            int c = col0 + wn * WN + nf * 8 + tg * 2;
            float b0 = bp[c], b1 = bp[c + 1];
            float v00 = acc[mf][nf][0] + b0, v01 = acc[mf][nf][1] + b1;
            float v10 = acc[mf][nf][2] + b0, v11 = acc[mf][nf][3] + b1;
            if (MODE == 1) {
                v00 = to_tf32(gelu_exact(v00)); v01 = to_tf32(gelu_exact(v01));
                v10 = to_tf32(gelu_exact(v10)); v11 = to_tf32(gelu_exact(v11));
            }
            if (MODE == 2) {
                v00 = to_tf32(v00); v01 = to_tf32(v01);
                v10 = to_tf32(v10); v11 = to_tf32(v11);
                int hh = c >> 6, dh = c & 63;
                int b_0 = r_lo >> 8, s_0 = r_lo & 255;
                int b_1 = (r_lo + 8) >> 8, s_1 = (r_lo + 8) & 255;
                *(float2*)&Cp[(((size_t)b_0 * H + hh) * SQ + s_0) * DH + dh] = make_float2(v00, v01);
                *(float2*)&Cp[(((size_t)b_1 * H + hh) * SQ + s_1) * DH + dh] = make_float2(v10, v11);
            } else {
                *(float2*)&Cp[(size_t)r_lo * N + c] = make_float2(v00, v01);
                *(float2*)&Cp[(size_t)(r_lo + 8) * N + c] = make_float2(v10, v11);
            }
        }
    }
}

// ============================================================================
// Fused attention with dual-stream axis (blockIdx.z).
// ============================================================================
#define PSTR 260
#define KVREG 4608
#define ATT_SMEM ((64*68 + 64*PSTR + KVREG) * (int)sizeof(float))

__global__ __launch_bounds__(256) void attn_fused(
    const float* __restrict__ QKVall,  // [stream][3][B,H,S,DH]
    const int* __restrict__ mask0, const int* __restrict__ mask1,
    float* __restrict__ outall)        // [stream][B,S,D]
{
    extern __shared__ float smem[];
    float* sQ = smem;
    float* sP = smem + 64 * 68;
    float* sKV = sP + 64 * PSTR;

    const int tid = threadIdx.x;
    const int lane = tid & 31, warp = tid >> 5;
    const int wm = warp >> 2, wn = warp & 3;
    const int g = lane >> 2, tg = lane & 3;

    const int stream = blockIdx.z;
    const float* QKV = QKVall + (size_t)stream * 3 * MD;
    const int* mask = stream ? mask1 : mask0;
    float* out = outall + (size_t)stream * MD;

    const int bh = blockIdx.x;
    const int b = bh / H, hh = bh % H;
    const int q0 = blockIdx.y * 64;

    const float* Qp = QKV + ((size_t)bh * SQ + q0) * DH;
    const float* Kp = QKV + MD + (size_t)bh * SQ * DH;
    const float* Vp = QKV + 2 * MD + (size_t)bh * SQ * DH;

    #pragma unroll
    for (int j = 0; j < 4; j++) {
        int f = tid + 256 * j;
        int r = f >> 4, c4 = (f & 15) << 2;
        *(float4*)&sQ[r * 68 + c4] = *(const float4*)&Qp[(size_t)r * DH + c4];
    }

    for (int stage = 0; stage < 4; stage++) {
        const int n0base = stage * 64;
        __syncthreads();
        #pragma unroll
        for (int j = 0; j < 4; j++) {
            int f = tid + 256 * j;
            int r = f >> 4, c4 = (f & 15) << 2;
            *(float4*)&sKV[r * 68 + c4] = *(const float4*)&Kp[(size_t)(n0base + r) * DH + c4];
        }
        __syncthreads();

        float acc[2][2][4] = {};
        #pragma unroll
        for (int ks = 0; ks < 8; ks++) {
            const int k8 = ks * 8;
            uint32_t a[2][4], bf[2][2];
            #pragma unroll
            for (int mf = 0; mf < 2; mf++) {
                int m0 = wm * 32 + mf * 16 + g;
                a[mf][0] = __float_as_uint(sQ[m0 * 68 + k8 + tg]);
                a[mf][1] = __float_as_uint(sQ[(m0 + 8) * 68 + k8 + tg]);
                a[mf][2] = __float_as_uint(sQ[m0 * 68 + k8 + tg + 4]);
                a[mf][3] = __float_as_uint(sQ[(m0 + 8) * 68 + k8 + tg + 4]);
            }
            #pragma unroll
            for (int nf = 0; nf < 2; nf++) {
                int n0 = wn * 16 + nf * 8 + g;
                bf[nf][0] = __float_as_uint(sKV[n0 * 68 + k8 + tg]);
                bf[nf][1] = __float_as_uint(sKV[n0 * 68 + k8 + tg + 4]);
            }
            #pragma unroll
            for (int mf = 0; mf < 2; mf++)
                #pragma unroll
                for (int nf = 0; nf < 2; nf++)
                    mma8(acc[mf][nf], a[mf][0], a[mf][1], a[mf][2], a[mf][3],
                         bf[nf][0], bf[nf][1]);
        }

        #pragma unroll
        for (int mf = 0; mf < 2; mf++) {
            int rloc = wm * 32 + mf * 16 + g;
            #pragma unroll
            for (int nf = 0; nf < 2; nf++) {
                int kk = n0base + wn * 16 + nf * 8 + tg * 2;
                float p0 = 10000.0f * (1.0f - (float)mask[b * SQ + kk]);
                float p1 = 10000.0f * (1.0f - (float)mask[b * SQ + kk + 1]);
                sP[rloc * PSTR + kk]           = acc[mf][nf][0] * 0.125f - p0;
                sP[rloc * PSTR + kk + 1]       = acc[mf][nf][1] * 0.125f - p1;
                sP[(rloc + 8) * PSTR + kk]     = acc[mf][nf][2] * 0.125f - p0;
                sP[(rloc + 8) * PSTR + kk + 1] = acc[mf][nf][3] * 0.125f - p1;
            }
        }
    }
    __syncthreads();

    for (int rr = 0; rr < 8; rr++) {
        int row = warp * 8 + rr;
        float* p = &sP[row * PSTR + lane * 8];
        float v[8];
        *(float4*)&v[0] = *(float4*)p;
        *(float4*)&v[4] = *(float4*)(p + 4);

        float mx = v[0];
        #pragma unroll
        for (int j = 1; j < 8; j++) mx = fmaxf(mx, v[j]);
        #pragma unroll
        for (int o = 16; o; o >>= 1) mx = fmaxf(mx, __shfl_xor_sync(0xffffffffu, mx, o));

        float s = 0.0f;
        #pragma unroll
        for (int j = 0; j < 8; j++) { v[j] = expf(v[j] - mx); s += v[j]; }
        #pragma unroll
        for (int o = 16; o; o >>= 1) s += __shfl_xor_sync(0xffffffffu, s, o);

        float inv = 1.0f / s;
        #pragma unroll
        for (int j = 0; j < 8; j++) v[j] = to_tf32(v[j] * inv);

        *(float4*)p = *(float4*)&v[0];
        *(float4*)(p + 4) = *(float4*)&v[4];
    }
    __syncthreads();

    float acc2[2][2][4] = {};
    #pragma unroll
    for (int j = 0; j < 2; j++) {
        int f = tid + 256 * j;
        int r = f >> 4, c4 = (f & 15) << 2;
        *(float4*)&sKV[r * 72 + c4] = *(const float4*)&Vp[(size_t)r * DH + c4];
    }
    __syncthreads();

    for (int c = 0; c < 8; c++) {
        const int buf = c & 1;
        const bool more = (c < 7);
        float4 vr[2];
        if (more) {
            #pragma unroll
            for (int j = 0; j < 2; j++) {
                int f = tid + 256 * j;
                int r = f >> 4, c4 = (f & 15) << 2;
                vr[j] = *(const float4*)&Vp[(size_t)((c + 1) * 32 + r) * DH + c4];
            }
        }

        const float* cV = &sKV[buf * 32 * 72];
        const int kbase = c * 32;
        #pragma unroll
        for (int ks = 0; ks < 4; ks++) {
            const int k8 = ks * 8;
            uint32_t a[2][4], bf[2][2];
            #pragma unroll
            for (int mf = 0; mf < 2; mf++) {
                int m0 = wm * 32 + mf * 16 + g;
                a[mf][0] = __float_as_uint(sP[m0 * PSTR + kbase + k8 + tg]);
                a[mf][1] = __float_as_uint(sP[(m0 + 8) * PSTR + kbase + k8 + tg]);
                a[mf][2] = __float_as_uint(sP[m0 * PSTR + kbase + k8 + tg + 4]);
                a[mf][3] = __float_as_uint(sP[(m0 + 8) * PSTR + kbase + k8 + tg + 4]);
            }
            #pragma unroll
            for (int nf = 0; nf < 2; nf++) {
                int n0 = wn * 16 + nf * 8 + g;
                bf[nf][0] = __float_as_uint(cV[(k8 + tg) * 72 + n0]);
                bf[nf][1] = __float_as_uint(cV[(k8 + tg + 4) * 72 + n0]);
            }
            #pragma unroll
            for (int mf = 0; mf < 2; mf++)
                #pragma unroll
                for (int nf = 0; nf < 2; nf++)
                    mma8(acc2[mf][nf], a[mf][0], a[mf][1], a[mf][2], a[mf][3],
                         bf[nf][0], bf[nf][1]);
        }

        if (more) {
            float* p0 = &sKV[(buf ^ 1) * 32 * 72];
            #pragma unroll
            for (int j = 0; j < 2; j++) {
                int f = tid + 256 * j;
                int r = f >> 4, c4 = (f & 15) << 2;
                *(float4*)&p0[r * 72 + c4] = vr[j];
            }
            __syncthreads();
        }
    }

    #pragma unroll
    for (int mf = 0; mf < 2; mf++) {
        int s = q0 + wm * 32 + mf * 16 + g;
        #pragma unroll
        for (int nf = 0; nf < 2; nf++) {
            int cc = hh * DH + wn * 16 + nf * 8 + tg * 2;
            *(float2*)&out[((size_t)b * SQ + s) * D + cc] =
                make_float2(acc2[mf][nf][0], acc2[mf][nf][1]);
            *(float2*)&out[((size_t)b * SQ + s + 8) * D + cc] =
                make_float2(acc2[mf][nf][2], acc2[mf][nf][3]);
        }
    }
}

// ---------------- residual add + LayerNorm (dual param-set) ----------------
// Single-stream launch: grid(M) -> set 0 only.  Dual launch: grid(2M).
__global__ __launch_bounds__(256) void addln_kernel(
    float* __restrict__ x0, const float* __restrict__ h0,
    const float* __restrict__ g0, const float* __restrict__ bta0,
    float* __restrict__ t0,
    float* __restrict__ x1, const float* __restrict__ h1,
    const float* __restrict__ g1, const float* __restrict__ bta1,
    float* __restrict__ t1)
{
    __shared__ float red[256];
    int row = blockIdx.x;
    float* x; const float* hbuf; const float* g; const float* bta; float* xt;
    if (row < M) { x = x0; hbuf = h0; g = g0; bta = bta0; xt = t0; }
    else { row -= M; x = x1; hbuf = h1; g = g1; bta = bta1; xt = t1; }

    const size_t base = (size_t)row * D;
    const int t = threadIdx.x;

    float v0 = x[base + t]       + hbuf[base + t];
    float v1 = x[base + t + 256] + hbuf[base + t + 256];
    float v2 = x[base + t + 512] + hbuf[base + t + 512];

    red[t] = v0 + v1 + v2;
    __syncthreads();
    for (int o = 128; o; o >>= 1) { if (t < o) red[t] += red[t + o]; __syncthreads(); }
    float mean = red[0] * (1.0f / 768.0f);
    __syncthreads();

    float d0 = v0 - mean, d1 = v1 - mean, d2 = v2 - mean;
    red[t] = d0 * d0 + d1 * d1 + d2 * d2;
    __syncthreads();
    for (int o = 128; o; o >>= 1) { if (t < o) red[t] += red[t + o]; __syncthreads(); }
    float inv = rsqrtf(red[0] * (1.0f / 768.0f) + 1e-12f);

    float r0 = d0 * inv * g[t]       + bta[t];
    float r1 = d1 * inv * g[t + 256] + bta[t + 256];
    float r2 = d2 * inv * g[t + 512] + bta[t + 512];
    x[base + t]        = r0;
    x[base + t + 256]  = r1;
    x[base + t + 512]  = r2;
    xt[base + t]       = to_tf32(r0);
    xt[base + t + 256] = to_tf32(r1);
    xt[base + t + 512] = to_tf32(r2);
}

// ---------------- host orchestration ----------------
static float *gx, *gy, *gxt, *gyt, *gqkv, *gh, *gffn;
static float *waxt, *wcxt, *wayt, *wcyt, *wfx1, *wfy1, *wfx2, *wfy2;
static bool g_resolved = false;

#define SMEM_CA128 (3*(128*36 + 32*136) * (int)sizeof(float))  // 107520
#define SMEM_CA64  (3*(128*36 + 32*72)  * (int)sizeof(float))  // 82944

static void resolve_symbols() {
    if (g_resolved) return;
    cudaGetSymbolAddress((void**)&gx,   g_x);
    cudaGetSymbolAddress((void**)&gy,   g_y);
    cudaGetSymbolAddress((void**)&gxt,  g_xt);
    cudaGetSymbolAddress((void**)&gyt,  g_yt);
    cudaGetSymbolAddress((void**)&gqkv, g_qkv);
    cudaGetSymbolAddress((void**)&gh,   g_h);
    cudaGetSymbolAddress((void**)&gffn, g_ffn);
    cudaGetSymbolAddress((void**)&waxt, g_axwt);
    cudaGetSymbolAddress((void**)&wcxt, g_cxwt);
    cudaGetSymbolAddress((void**)&wayt, g_aywt);
    cudaGetSymbolAddress((void**)&wcyt, g_cywt);
    cudaGetSymbolAddress((void**)&wfx1, g_fxw1t);
    cudaGetSymbolAddress((void**)&wfy1, g_fyw1t);
    cudaGetSymbolAddress((void**)&wfx2, g_fxw2t);
    cudaGetSymbolAddress((void**)&wfy2, g_fyw2t);
    cudaFuncSetAttribute(gemm_ca<128,2>, cudaFuncAttributeMaxDynamicSharedMemorySize, SMEM_CA128);
    cudaFuncSetAttribute(gemm_ca<128,1>, cudaFuncAttributeMaxDynamicSharedMemorySize, SMEM_CA128);
    cudaFuncSetAttribute(gemm_ca<64,0>,  cudaFuncAttributeMaxDynamicSharedMemorySize, SMEM_CA64);
    cudaFuncSetAttribute(attn_fused,     cudaFuncAttributeMaxDynamicSharedMemorySize, ATT_SMEM);
    g_resolved = true;
}

extern "C" void kernel_launch(void* const* d_in, const int* in_sizes, int n_in,
                              void* d_out, int out_size)
{
    const float* x     = (const float*)d_in[0];
    const float* y     = (const float*)d_in[1];
    const int*   xmask = (const int*)  d_in[2];
    const int*   ymask = (const int*)  d_in[3];
    const float* ax_w  = (const float*)d_in[4];
    const float* ax_b  = (const float*)d_in[5];
    const float* cx_w  = (const float*)d_in[6];
    const float* cx_b  = (const float*)d_in[7];
    const float* fx_w1 = (const float*)d_in[8];
    const float* fx_b1 = (const float*)d_in[9];
    const float* fx_w2 = (const float*)d_in[10];
    const float* fx_b2 = (const float*)d_in[11];
    const float* ay_w  = (const float*)d_in[12];
    const float* ay_b  = (const float*)d_in[13];
    const float* cy_w  = (const float*)d_in[14];
    const float* cy_b  = (const float*)d_in[15];
    const float* fy_w1 = (const float*)d_in[16];
    const float* fy_b1 = (const float*)d_in[17];
    const float* fy_w2 = (const float*)d_in[18];
    const float* fy_b2 = (const float*)d_in[19];
    const float* lnx_g = (const float*)d_in[20];
    const float* lnx_b = (const float*)d_in[21];
    const float* lny_g = (const float*)d_in[22];
    const float* lny_b = (const float*)d_in[23];

    resolve_symbols();

    // pre-round weights + stream state to tf32
    {
        const int na4 = WA_N / 4, nf4 = WF_N / 4, nx4 = (int)(MD / 4);
        cvt4x4_kernel<<<dim3((na4 + 255) / 256, 4), 256>>>(
            (const float4*)ax_w, (float4*)waxt,
            (const float4*)cx_w, (float4*)wcxt,
            (const float4*)ay_w, (float4*)wayt,
            (const float4*)cy_w, (float4*)wcyt, na4);
        cvt4x4_kernel<<<dim3((nf4 + 255) / 256, 4), 256>>>(
            (const float4*)fx_w1, (float4*)wfx1,
            (const float4*)fy_w1, (float4*)wfy1,
            (const float4*)fx_w2, (float4*)wfx2,
            (const float4*)fy_w2, (float4*)wfy2, nf4);
        copycvt4_kernel<<<dim3((nx4 + 255) / 256, 2), 256>>>(
            (const float4*)x, (float4*)gx, (float4*)gxt,
            (const float4*)y, (float4*)gy, (float4*)gyt, nx4);
    }

    const size_t QS = 3 * MD;   // qkv per-stream stride

    for (int l = 0; l < 6; l++) {
        const float* axw = waxt + (size_t)l * 3 * D * D;
        const float* axb = ax_b + (size_t)l * 3 * D;
        const float* ayw = wayt + (size_t)l * 3 * D * D;
        const float* ayb = ay_b + (size_t)l * 3 * D;
        const float* cxw = wcxt + (size_t)l * 3 * D * D;
        const float* cxb = cx_b + (size_t)l * 3 * D;
        const float* cyw = wcyt + (size_t)l * 3 * D * D;
        const float* cyb = cy_b + (size_t)l * 3 * D;
        const float* fxw1 = wfx1 + (size_t)l * D * FF;
        const float* fxb1 = fx_b1 + (size_t)l * FF;
        const float* fxw2 = wfx2 + (size_t)l * FF * D;
        const float* fxb2 = fx_b2 + (size_t)l * D;
        const float* fyw1 = wfy1 + (size_t)l * D * FF;
        const float* fyb1 = fy_b1 + (size_t)l * FF;
        const float* fyw2 = wfy2 + (size_t)l * FF * D;
        const float* fyb2 = fy_b2 + (size_t)l * D;

        // ---- self-attention x + y (fused dual-stream) ----
        gemm_ca<128,2><<<dim3(18, 16, 2), 256, SMEM_CA128>>>(
            gxt, gxt, gyt, gyt, axw, ayw, axb, ayb, gqkv, D, D, QS);
        attn_fused<<<dim3(BB * H, SQ / 64, 2), 256, ATT_SMEM>>>(gqkv, xmask, ymask, gh);
        addln_kernel<<<2 * M, 256>>>(
            gx, gh, lnx_g + 0 * D, lnx_b + 0 * D, gxt,
            gy, gh + MD, lny_g + 0 * D, lny_b + 0 * D, gyt);

        // ---- cross x (q from x, kv from updated y) ----
        gemm_ca<128,2><<<dim3(18, 16, 1), 256, SMEM_CA128>>>(
            gxt, gyt, gxt, gyt, cxw, cxw, cxb, cxb, gqkv, D, D, QS);
        attn_fused<<<dim3(BB * H, SQ / 64, 1), 256, ATT_SMEM>>>(gqkv, ymask, ymask, gh);
        addln_kernel<<<M, 256>>>(
            gx, gh, lnx_g + 1 * D, lnx_b + 1 * D, gxt,
            gx, gh, lnx_g + 1 * D, lnx_b + 1 * D, gxt);

        // ---- cross y (q from y, kv from updated x) ----
        gemm_ca<128,2><<<dim3(18, 16, 1), 256, SMEM_CA128>>>(
            gyt, gxt, gyt, gxt, cyw, cyw, cyb, cyb, gqkv, D, D, QS);
        attn_fused<<<dim3(BB * H, SQ / 64, 1), 256, ATT_SMEM>>>(gqkv, xmask, xmask, gh);
        addln_kernel<<<M, 256>>>(
            gy, gh, lny_g + 1 * D, lny_b + 1 * D, gyt,
            gy, gh, lny_g + 1 * D, lny_b + 1 * D, gyt);

        // ---- FFN x + y (fused dual-stream) ----
        gemm_ca<128,1><<<dim3(FF / 128, 16, 2), 256, SMEM_CA128>>>(
            gxt, gxt, gyt, gyt, fxw1, fyw1, fxb1, fyb1, gffn, FF, D, (size_t)M * FF);
        gemm_ca<64,0><<<dim3(D / 64, 16, 2), 256, SMEM_CA64>>>(
            gffn, gffn, gffn + (size_t)M * FF, gffn + (size_t)M * FF,
            fxw2, fyw2, fxb2, fyb2, gh, D, FF, MD);
        addln_kernel<<<2 * M, 256>>>(
            gx, gh, lnx_g + 2 * D, lnx_b + 2 * D, gxt,
            gy, gh + MD, lny_g + 2 * D, lny_b + 2 * D, gyt);
    }

    cudaMemcpyAsync((float*)d_out,      gx, MD * sizeof(float), cudaMemcpyDeviceToDevice, 0);
    cudaMemcpyAsync((float*)d_out + MD, gy, MD * sizeof(float), cudaMemcpyDeviceToDevice, 0);
}

// round 13
// speedup vs baseline: 1.2972x; 1.0755x over previous
#include <cuda_runtime.h>
#include <math.h>
#include <stdint.h>

// Problem dims
#define D   768
#define H   12
#define SQ  256
#define BB  8
#define DH  64
#define M   (BB*SQ)     // 2048 rows
#define FF  (4*D)       // 3072
#define MD  ((size_t)M*D)

#define WA_N  (6*3*D*D)
#define WF_N  (6*D*FF)

// ---------------- scratch (device globals; no allocs allowed) ----------------
__device__ float g_x[M*D];        // fp32 stream state
__device__ float g_y[M*D];
__device__ float g_xt[M*D];       // tf32-rounded copy (GEMM A operand)
__device__ float g_yt[M*D];
__device__ float g_qkv[6*M*D];    // [2 streams][3][B,H,S,DH] (tf32)
__device__ float g_h[2*M*D];      // attn/ffn2 output (fp32), per stream
__device__ float g_ffn[(size_t)2*M*FF]; // ffn hidden (tf32), per stream

// pre-converted (tf32-rounded) weights
__device__ float g_axwt[WA_N];
__device__ float g_cxwt[WA_N];
__device__ float g_aywt[WA_N];
__device__ float g_cywt[WA_N];
__device__ float g_fxw1t[WF_N];
__device__ float g_fyw1t[WF_N];
__device__ float g_fxw2t[WF_N];
__device__ float g_fyw2t[WF_N];

// ---------------- tf32 helpers ----------------
__device__ __forceinline__ float to_tf32(float x) {
    float r;
    asm("cvt.rna.tf32.f32 %0, %1;" : "=f"(r) : "f"(x));
    return r;
}

__device__ __forceinline__ void mma8(float c[4],
    uint32_t a0, uint32_t a1, uint32_t a2, uint32_t a3,
    uint32_t b0, uint32_t b1)
{
    asm volatile(
        "mma.sync.aligned.m16n8k8.row.col.f32.tf32.tf32.f32 "
        "{%0,%1,%2,%3}, {%4,%5,%6,%7}, {%8,%9}, {%0,%1,%2,%3};"
        : "+f"(c[0]), "+f"(c[1]), "+f"(c[2]), "+f"(c[3])
        : "r"(a0), "r"(a1), "r"(a2), "r"(a3), "r"(b0), "r"(b1));
}

__device__ __forceinline__ float gelu_exact(float v) {
    return 0.5f * v * (1.0f + erff(v * 0.70710678118654752f));
}

#define CP16(dst, src) \
    asm volatile("cp.async.cg.shared.global [%0], [%1], 16;\n" :: "r"(dst), "l"(src))
#define CP_COMMIT() asm volatile("cp.async.commit_group;\n" ::: "memory")
#define CP_WAIT1()  asm volatile("cp.async.wait_group 1;\n" ::: "memory")

// ---------------- conversion kernels (4 tensors per launch) ----------------
__global__ void cvt4x4_kernel(const float4* __restrict__ i0, float4* __restrict__ o0,
                              const float4* __restrict__ i1, float4* __restrict__ o1,
                              const float4* __restrict__ i2, float4* __restrict__ o2,
                              const float4* __restrict__ i3, float4* __restrict__ o3,
                              int n4)
{
    int i = blockIdx.x * 256 + threadIdx.x;
    if (i >= n4) return;
    const float4* in; float4* out;
    switch (blockIdx.y) {
        case 0: in = i0; out = o0; break;
        case 1: in = i1; out = o1; break;
        case 2: in = i2; out = o2; break;
        default: in = i3; out = o3; break;
    }
    float4 v = in[i];
    v.x = to_tf32(v.x); v.y = to_tf32(v.y);
    v.z = to_tf32(v.z); v.w = to_tf32(v.w);
    out[i] = v;
}

__global__ void copycvt4_kernel(const float4* __restrict__ i0, float4* __restrict__ f0, float4* __restrict__ t0,
                                const float4* __restrict__ i1, float4* __restrict__ f1, float4* __restrict__ t1,
                                int n4)
{
    int i = blockIdx.x * 256 + threadIdx.x;
    if (i >= n4) return;
    const float4* in; float4 *outf, *outt;
    if (blockIdx.y == 0) { in = i0; outf = f0; outt = t0; }
    else                 { in = i1; outf = f1; outt = t1; }
    float4 v = in[i];
    outf[i] = v;
    v.x = to_tf32(v.x); v.y = to_tf32(v.y);
    v.z = to_tf32(v.z); v.w = to_tf32(v.w);
    outt[i] = v;
}

// ============================================================================
// 3-stage cp.async tf32 GEMM with dual-stream axis (blockIdx.z).
// Block tile 128 x BN, BK=32, 256 threads, 8 warps 2(m) x 4(n).
// __launch_bounds__(256, 2): cap regs at 128 so TWO CTAs co-reside per SM
// (smem 107.5KB x 2 = 215KB fits under 228KB) — hides sync/cp.async stalls.
// MODE: 0 = plain+bias (fp32 out), 1 = bias+GELU (tf32 out),
//       2 = QKV fused (tf32 out, scatter, N==768).
// ============================================================================
template<int BN, int MODE>
__global__ __launch_bounds__(256, 2) void gemm_ca(
    const float* __restrict__ A0q, const float* __restrict__ A0kv,
    const float* __restrict__ A1q, const float* __restrict__ A1kv,
    const float* __restrict__ W0, const float* __restrict__ W1,
    const float* __restrict__ b0s, const float* __restrict__ b1s,
    float* __restrict__ C, int N, int K, size_t cstride)
{
    constexpr int BP = BN + 8;
    constexpr int NF = BN / 32;
    constexpr int WN = BN / 4;
    constexpr int NB4 = BN / 32;
    constexpr int ASZ = 128 * 36;
    constexpr int BSZ = 32 * BP;

    extern __shared__ float smem[];
    float* sA = smem;            // [3][128][36]
    float* sB = smem + 3 * ASZ;  // [3][32][BP]

    const int tid = threadIdx.x;
    const int lane = tid & 31, warp = tid >> 5;
    const int wm = warp >> 2, wn = warp & 3;
    const int g = lane >> 2, tg = lane & 3;
    const int row0 = blockIdx.y * 128;
    const int stream = blockIdx.z;

    const float* Aq  = stream ? A1q  : A0q;
    const float* Akv = stream ? A1kv : A0kv;
    const float* Wbase = stream ? W1 : W0;
    const float* bbase = stream ? b1s : b0s;
    float* Cbase = C + (size_t)stream * cstride;

    const float* A; const float* Wp; const float* bp; float* Cp; int col0;
    if (MODE == 2) {
        const int perMat = 768 / BN;
        const int mat = blockIdx.x / perMat;
        col0 = (blockIdx.x % perMat) * BN;
        A  = (mat == 0) ? Aq : Akv;
        Wp = Wbase + (size_t)mat * D * D;
        bp = bbase + mat * D;
        Cp = Cbase + (size_t)mat * MD;
    } else {
        col0 = blockIdx.x * BN;
        A = Aq; Wp = Wbase; bp = bbase; Cp = Cbase;
    }

    const uint32_t sAu = (uint32_t)__cvta_generic_to_shared(sA);
    const uint32_t sBu = (uint32_t)__cvta_generic_to_shared(sB);

    float acc[4][NF][4] = {};

    #define ISSUE(ST, K0) { \
        _Pragma("unroll") \
        for (int j = 0; j < 4; j++) { \
            int f = tid + 256 * j; \
            int r = f >> 3, c4 = (f & 7) << 2; \
            uint32_t dst = sAu + (uint32_t)(((ST) * ASZ + r * 36 + c4) * 4); \
            CP16(dst, &A[(size_t)(row0 + r) * K + (K0) + c4]); \
        } \
        _Pragma("unroll") \
        for (int j = 0; j < NB4; j++) { \
            int f = tid + 256 * j; \
            int r = f / (BN / 4), c4 = (f % (BN / 4)) << 2; \
            uint32_t dst = sBu + (uint32_t)(((ST) * BSZ + r * BP + c4) * 4); \
            CP16(dst, &Wp[(size_t)((K0) + r) * N + col0 + c4]); \
        } }

    ISSUE(0, 0);
    CP_COMMIT();
    ISSUE(1, 32);
    CP_COMMIT();

    const int kt = K >> 5;
    for (int i = 0; i < kt; i++) {
        CP_WAIT1();
        __syncthreads();

        const float* cA = &sA[(i % 3) * ASZ];
        const float* cB = &sB[(i % 3) * BSZ];
        #pragma unroll
        for (int ks = 0; ks < 4; ks++) {
            const int k8 = ks * 8;
            uint32_t a[4][4], b[NF][2];
            #pragma unroll
            for (int mf = 0; mf < 4; mf++) {
                int m0 = wm * 64 + mf * 16 + g;
                a[mf][0] = __float_as_uint(cA[m0 * 36 + k8 + tg]);
                a[mf][1] = __float_as_uint(cA[(m0 + 8) * 36 + k8 + tg]);
                a[mf][2] = __float_as_uint(cA[m0 * 36 + k8 + tg + 4]);
                a[mf][3] = __float_as_uint(cA[(m0 + 8) * 36 + k8 + tg + 4]);
            }
            #pragma unroll
            for (int nf = 0; nf < NF; nf++) {
                int n0 = wn * WN + nf * 8 + g;
                b[nf][0] = __float_as_uint(cB[(k8 + tg) * BP + n0]);
                b[nf][1] = __float_as_uint(cB[(k8 + tg + 4) * BP + n0]);
            }
            #pragma unroll
            for (int mf = 0; mf < 4; mf++)
                #pragma unroll
                for (int nf = 0; nf < NF; nf++)
                    mma8(acc[mf][nf], a[mf][0], a[mf][1], a[mf][2], a[mf][3],
                         b[nf][0], b[nf][1]);
        }

        const int nk = i + 2;
        if (nk < kt) ISSUE(nk % 3, nk << 5);
        CP_COMMIT();
    }

    #undef ISSUE

    // ---- epilogue ----
    #pragma unroll
    for (int mf = 0; mf < 4; mf++) {
        int r_lo = row0 + wm * 64 + mf * 16 + g;
        #pragma unroll
        for (int nf = 0; nf < NF; nf++) {
            int c = col0 + wn * WN + nf * 8 + tg * 2;
            float b0 = bp[c], b1 = bp[c + 1];
            float v00 = acc[mf][nf][0] + b0, v01 = acc[mf][nf][1] + b1;
            float v10 = acc[mf][nf][2] + b0, v11 = acc[mf][nf][3] + b1;
            if (MODE == 1) {
                v00 = to_tf32(gelu_exact(v00)); v01 = to_tf32(gelu_exact(v01));
                v10 = to_tf32(gelu_exact(v10)); v11 = to_tf32(gelu_exact(v11));
            }
            if (MODE == 2) {
                v00 = to_tf32(v00); v01 = to_tf32(v01);
                v10 = to_tf32(v10); v11 = to_tf32(v11);
                int hh = c >> 6, dh = c & 63;
                int b_0 = r_lo >> 8, s_0 = r_lo & 255;
                int b_1 = (r_lo + 8) >> 8, s_1 = (r_lo + 8) & 255;
                *(float2*)&Cp[(((size_t)b_0 * H + hh) * SQ + s_0) * DH + dh] = make_float2(v00, v01);
                *(float2*)&Cp[(((size_t)b_1 * H + hh) * SQ + s_1) * DH + dh] = make_float2(v10, v11);
            } else {
                *(float2*)&Cp[(size_t)r_lo * N + c] = make_float2(v00, v01);
                *(float2*)&Cp[(size_t)(r_lo + 8) * N + c] = make_float2(v10, v11);
            }
        }
    }
}

// ============================================================================
// Fused attention with dual-stream axis (blockIdx.z). 2 CTAs/SM.
// ============================================================================
#define PSTR 260
#define KVREG 4608
#define ATT_SMEM ((64*68 + 64*PSTR + KVREG) * (int)sizeof(float))

__global__ __launch_bounds__(256, 2) void attn_fused(
    const float* __restrict__ QKVall,  // [stream][3][B,H,S,DH]
    const int* __restrict__ mask0, const int* __restrict__ mask1,
    float* __restrict__ outall)        // [stream][B,S,D]
{
    extern __shared__ float smem[];
    float* sQ = smem;
    float* sP = smem + 64 * 68;
    float* sKV = sP + 64 * PSTR;

    const int tid = threadIdx.x;
    const int lane = tid & 31, warp = tid >> 5;
    const int wm = warp >> 2, wn = warp & 3;
    const int g = lane >> 2, tg = lane & 3;

    const int stream = blockIdx.z;
    const float* QKV = QKVall + (size_t)stream * 3 * MD;
    const int* mask = stream ? mask1 : mask0;
    float* out = outall + (size_t)stream * MD;

    const int bh = blockIdx.x;
    const int b = bh / H, hh = bh % H;
    const int q0 = blockIdx.y * 64;

    const float* Qp = QKV + ((size_t)bh * SQ + q0) * DH;
    const float* Kp = QKV + MD + (size_t)bh * SQ * DH;
    const float* Vp = QKV + 2 * MD + (size_t)bh * SQ * DH;

    #pragma unroll
    for (int j = 0; j < 4; j++) {
        int f = tid + 256 * j;
        int r = f >> 4, c4 = (f & 15) << 2;
        *(float4*)&sQ[r * 68 + c4] = *(const float4*)&Qp[(size_t)r * DH + c4];
    }

    for (int stage = 0; stage < 4; stage++) {
        const int n0base = stage * 64;
        __syncthreads();
        #pragma unroll
        for (int j = 0; j < 4; j++) {
            int f = tid + 256 * j;
            int r = f >> 4, c4 = (f & 15) << 2;
            *(float4*)&sKV[r * 68 + c4] = *(const float4*)&Kp[(size_t)(n0base + r) * DH + c4];
        }
        __syncthreads();

        float acc[2][2][4] = {};
        #pragma unroll
        for (int ks = 0; ks < 8; ks++) {
            const int k8 = ks * 8;
            uint32_t a[2][4], bf[2][2];
            #pragma unroll
            for (int mf = 0; mf < 2; mf++) {
                int m0 = wm * 32 + mf * 16 + g;
                a[mf][0] = __float_as_uint(sQ[m0 * 68 + k8 + tg]);
                a[mf][1] = __float_as_uint(sQ[(m0 + 8) * 68 + k8 + tg]);
                a[mf][2] = __float_as_uint(sQ[m0 * 68 + k8 + tg + 4]);
                a[mf][3] = __float_as_uint(sQ[(m0 + 8) * 68 + k8 + tg + 4]);
            }
            #pragma unroll
            for (int nf = 0; nf < 2; nf++) {
                int n0 = wn * 16 + nf * 8 + g;
                bf[nf][0] = __float_as_uint(sKV[n0 * 68 + k8 + tg]);
                bf[nf][1] = __float_as_uint(sKV[n0 * 68 + k8 + tg + 4]);
            }
            #pragma unroll
            for (int mf = 0; mf < 2; mf++)
                #pragma unroll
                for (int nf = 0; nf < 2; nf++)
                    mma8(acc[mf][nf], a[mf][0], a[mf][1], a[mf][2], a[mf][3],
                         bf[nf][0], bf[nf][1]);
        }

        #pragma unroll
        for (int mf = 0; mf < 2; mf++) {
            int rloc = wm * 32 + mf * 16 + g;
            #pragma unroll
            for (int nf = 0; nf < 2; nf++) {
                int kk = n0base + wn * 16 + nf * 8 + tg * 2;
                float p0 = 10000.0f * (1.0f - (float)mask[b * SQ + kk]);
                float p1 = 10000.0f * (1.0f - (float)mask[b * SQ + kk + 1]);
                sP[rloc * PSTR + kk]           = acc[mf][nf][0] * 0.125f - p0;
                sP[rloc * PSTR + kk + 1]       = acc[mf][nf][1] * 0.125f - p1;
                sP[(rloc + 8) * PSTR + kk]     = acc[mf][nf][2] * 0.125f - p0;
                sP[(rloc + 8) * PSTR + kk + 1] = acc[mf][nf][3] * 0.125f - p1;
            }
        }
    }
    __syncthreads();

    for (int rr = 0; rr < 8; rr++) {
        int row = warp * 8 + rr;
        float* p = &sP[row * PSTR + lane * 8];
        float v[8];
        *(float4*)&v[0] = *(float4*)p;
        *(float4*)&v[4] = *(float4*)(p + 4);

        float mx = v[0];
        #pragma unroll
        for (int j = 1; j < 8; j++) mx = fmaxf(mx, v[j]);
        #pragma unroll
        for (int o = 16; o; o >>= 1) mx = fmaxf(mx, __shfl_xor_sync(0xffffffffu, mx, o));

        float s = 0.0f;
        #pragma unroll
        for (int j = 0; j < 8; j++) { v[j] = expf(v[j] - mx); s += v[j]; }
        #pragma unroll
        for (int o = 16; o; o >>= 1) s += __shfl_xor_sync(0xffffffffu, s, o);

        float inv = 1.0f / s;
        #pragma unroll
        for (int j = 0; j < 8; j++) v[j] = to_tf32(v[j] * inv);

        *(float4*)p = *(float4*)&v[0];
        *(float4*)(p + 4) = *(float4*)&v[4];
    }
    __syncthreads();

    float acc2[2][2][4] = {};
    #pragma unroll
    for (int j = 0; j < 2; j++) {
        int f = tid + 256 * j;
        int r = f >> 4, c4 = (f & 15) << 2;
        *(float4*)&sKV[r * 72 + c4] = *(const float4*)&Vp[(size_t)r * DH + c4];
    }
    __syncthreads();

    for (int c = 0; c < 8; c++) {
        const int buf = c & 1;
        const bool more = (c < 7);
        float4 vr[2];
        if (more) {
            #pragma unroll
            for (int j = 0; j < 2; j++) {
                int f = tid + 256 * j;
                int r = f >> 4, c4 = (f & 15) << 2;
                vr[j] = *(const float4*)&Vp[(size_t)((c + 1) * 32 + r) * DH + c4];
            }
        }

        const float* cV = &sKV[buf * 32 * 72];
        const int kbase = c * 32;
        #pragma unroll
        for (int ks = 0; ks < 4; ks++) {
            const int k8 = ks * 8;
            uint32_t a[2][4], bf[2][2];
            #pragma unroll
            for (int mf = 0; mf < 2; mf++) {
                int m0 = wm * 32 + mf * 16 + g;
                a[mf][0] = __float_as_uint(sP[m0 * PSTR + kbase + k8 + tg]);
                a[mf][1] = __float_as_uint(sP[(m0 + 8) * PSTR + kbase + k8 + tg]);
                a[mf][2] = __float_as_uint(sP[m0 * PSTR + kbase + k8 + tg + 4]);
                a[mf][3] = __float_as_uint(sP[(m0 + 8) * PSTR + kbase + k8 + tg + 4]);
            }
            #pragma unroll
            for (int nf = 0; nf < 2; nf++) {
                int n0 = wn * 16 + nf * 8 + g;
                bf[nf][0] = __float_as_uint(cV[(k8 + tg) * 72 + n0]);
                bf[nf][1] = __float_as_uint(cV[(k8 + tg + 4) * 72 + n0]);
            }
            #pragma unroll
            for (int mf = 0; mf < 2; mf++)
                #pragma unroll
                for (int nf = 0; nf < 2; nf++)
                    mma8(acc2[mf][nf], a[mf][0], a[mf][1], a[mf][2], a[mf][3],
                         bf[nf][0], bf[nf][1]);
        }

        if (more) {
            float* p0 = &sKV[(buf ^ 1) * 32 * 72];
            #pragma unroll
            for (int j = 0; j < 2; j++) {
                int f = tid + 256 * j;
                int r = f >> 4, c4 = (f & 15) << 2;
                *(float4*)&p0[r * 72 + c4] = vr[j];
            }
            __syncthreads();
        }
    }

    #pragma unroll
    for (int mf = 0; mf < 2; mf++) {
        int s = q0 + wm * 32 + mf * 16 + g;
        #pragma unroll
        for (int nf = 0; nf < 2; nf++) {
            int cc = hh * DH + wn * 16 + nf * 8 + tg * 2;
            *(float2*)&out[((size_t)b * SQ + s) * D + cc] =
                make_float2(acc2[mf][nf][0], acc2[mf][nf][1]);
            *(float2*)&out[((size_t)b * SQ + s + 8) * D + cc] =
                make_float2(acc2[mf][nf][2], acc2[mf][nf][3]);
        }
    }
}

// ---------------- residual add + LayerNorm (dual param-set) ----------------
__global__ __launch_bounds__(256) void addln_kernel(
    float* __restrict__ x0, const float* __restrict__ h0,
    const float* __restrict__ g0, const float* __restrict__ bta0,
    float* __restrict__ t0,
    float* __restrict__ x1, const float* __restrict__ h1,
    const float* __restrict__ g1, const float* __restrict__ bta1,
    float* __restrict__ t1)
{
    __shared__ float red[256];
    int row = blockIdx.x;
    float* x; const float* hbuf; const float* g; const float* bta; float* xt;
    if (row < M) { x = x0; hbuf = h0; g = g0; bta = bta0; xt = t0; }
    else { row -= M; x = x1; hbuf = h1; g = g1; bta = bta1; xt = t1; }

    const size_t base = (size_t)row * D;
    const int t = threadIdx.x;

    float v0 = x[base + t]       + hbuf[base + t];
    float v1 = x[base + t + 256] + hbuf[base + t + 256];
    float v2 = x[base + t + 512] + hbuf[base + t + 512];

    red[t] = v0 + v1 + v2;
    __syncthreads();
    for (int o = 128; o; o >>= 1) { if (t < o) red[t] += red[t + o]; __syncthreads(); }
    float mean = red[0] * (1.0f / 768.0f);
    __syncthreads();

    float d0 = v0 - mean, d1 = v1 - mean, d2 = v2 - mean;
    red[t] = d0 * d0 + d1 * d1 + d2 * d2;
    __syncthreads();
    for (int o = 128; o; o >>= 1) { if (t < o) red[t] += red[t + o]; __syncthreads(); }
    float inv = rsqrtf(red[0] * (1.0f / 768.0f) + 1e-12f);

    float r0 = d0 * inv * g[t]       + bta[t];
    float r1 = d1 * inv * g[t + 256] + bta[t + 256];
    float r2 = d2 * inv * g[t + 512] + bta[t + 512];
    x[base + t]        = r0;
    x[base + t + 256]  = r1;
    x[base + t + 512]  = r2;
    xt[base + t]       = to_tf32(r0);
    xt[base + t + 256] = to_tf32(r1);
    xt[base + t + 512] = to_tf32(r2);
}

// ---------------- host orchestration ----------------
static float *gx, *gy, *gxt, *gyt, *gqkv, *gh, *gffn;
static float *waxt, *wcxt, *wayt, *wcyt, *wfx1, *wfy1, *wfx2, *wfy2;
static bool g_resolved = false;

#define SMEM_CA128 (3*(128*36 + 32*136) * (int)sizeof(float))  // 107520
#define SMEM_CA64  (3*(128*36 + 32*72)  * (int)sizeof(float))  // 82944

static void resolve_symbols() {
    if (g_resolved) return;
    cudaGetSymbolAddress((void**)&gx,   g_x);
    cudaGetSymbolAddress((void**)&gy,   g_y);
    cudaGetSymbolAddress((void**)&gxt,  g_xt);
    cudaGetSymbolAddress((void**)&gyt,  g_yt);
    cudaGetSymbolAddress((void**)&gqkv, g_qkv);
    cudaGetSymbolAddress((void**)&gh,   g_h);
    cudaGetSymbolAddress((void**)&gffn, g_ffn);
    cudaGetSymbolAddress((void**)&waxt, g_axwt);
    cudaGetSymbolAddress((void**)&wcxt, g_cxwt);
    cudaGetSymbolAddress((void**)&wayt, g_aywt);
    cudaGetSymbolAddress((void**)&wcyt, g_cywt);
    cudaGetSymbolAddress((void**)&wfx1, g_fxw1t);
    cudaGetSymbolAddress((void**)&wfy1, g_fyw1t);
    cudaGetSymbolAddress((void**)&wfx2, g_fxw2t);
    cudaGetSymbolAddress((void**)&wfy2, g_fyw2t);
    cudaFuncSetAttribute(gemm_ca<128,2>, cudaFuncAttributeMaxDynamicSharedMemorySize, SMEM_CA128);
    cudaFuncSetAttribute(gemm_ca<128,1>, cudaFuncAttributeMaxDynamicSharedMemorySize, SMEM_CA128);
    cudaFuncSetAttribute(gemm_ca<64,0>,  cudaFuncAttributeMaxDynamicSharedMemorySize, SMEM_CA64);
    cudaFuncSetAttribute(attn_fused,     cudaFuncAttributeMaxDynamicSharedMemorySize, ATT_SMEM);
    g_resolved = true;
}

extern "C" void kernel_launch(void* const* d_in, const int* in_sizes, int n_in,
                              void* d_out, int out_size)
{
    const float* x     = (const float*)d_in[0];
    const float* y     = (const float*)d_in[1];
    const int*   xmask = (const int*)  d_in[2];
    const int*   ymask = (const int*)  d_in[3];
    const float* ax_w  = (const float*)d_in[4];
    const float* ax_b  = (const float*)d_in[5];
    const float* cx_w  = (const float*)d_in[6];
    const float* cx_b  = (const float*)d_in[7];
    const float* fx_w1 = (const float*)d_in[8];
    const float* fx_b1 = (const float*)d_in[9];
    const float* fx_w2 = (const float*)d_in[10];
    const float* fx_b2 = (const float*)d_in[11];
    const float* ay_w  = (const float*)d_in[12];
    const float* ay_b  = (const float*)d_in[13];
    const float* cy_w  = (const float*)d_in[14];
    const float* cy_b  = (const float*)d_in[15];
    const float* fy_w1 = (const float*)d_in[16];
    const float* fy_b1 = (const float*)d_in[17];
    const float* fy_w2 = (const float*)d_in[18];
    const float* fy_b2 = (const float*)d_in[19];
    const float* lnx_g = (const float*)d_in[20];
    const float* lnx_b = (const float*)d_in[21];
    const float* lny_g = (const float*)d_in[22];
    const float* lny_b = (const float*)d_in[23];

    resolve_symbols();

    // pre-round weights + stream state to tf32
    {
        const int na4 = WA_N / 4, nf4 = WF_N / 4, nx4 = (int)(MD / 4);
        cvt4x4_kernel<<<dim3((na4 + 255) / 256, 4), 256>>>(
            (const float4*)ax_w, (float4*)waxt,
            (const float4*)cx_w, (float4*)wcxt,
            (const float4*)ay_w, (float4*)wayt,
            (const float4*)cy_w, (float4*)wcyt, na4);
        cvt4x4_kernel<<<dim3((nf4 + 255) / 256, 4), 256>>>(
            (const float4*)fx_w1, (float4*)wfx1,
            (const float4*)fy_w1, (float4*)wfy1,
            (const float4*)fx_w2, (float4*)wfx2,
            (const float4*)fy_w2, (float4*)wfy2, nf4);
        copycvt4_kernel<<<dim3((nx4 + 255) / 256, 2), 256>>>(
            (const float4*)x, (float4*)gx, (float4*)gxt,
            (const float4*)y, (float4*)gy, (float4*)gyt, nx4);
    }

    const size_t QS = 3 * MD;   // qkv per-stream stride

    for (int l = 0; l < 6; l++) {
        const float* axw = waxt + (size_t)l * 3 * D * D;
        const float* axb = ax_b + (size_t)l * 3 * D;
        const float* ayw = wayt + (size_t)l * 3 * D * D;
        const float* ayb = ay_b + (size_t)l * 3 * D;
        const float* cxw = wcxt + (size_t)l * 3 * D * D;
        const float* cxb = cx_b + (size_t)l * 3 * D;
        const float* cyw = wcyt + (size_t)l * 3 * D * D;
        const float* cyb = cy_b + (size_t)l * 3 * D;
        const float* fxw1 = wfx1 + (size_t)l * D * FF;
        const float* fxb1 = fx_b1 + (size_t)l * FF;
        const float* fxw2 = wfx2 + (size_t)l * FF * D;
        const float* fxb2 = fx_b2 + (size_t)l * D;
        const float* fyw1 = wfy1 + (size_t)l * D * FF;
        const float* fyb1 = fy_b1 + (size_t)l * FF;
        const float* fyw2 = wfy2 + (size_t)l * FF * D;
        const float* fyb2 = fy_b2 + (size_t)l * D;

        // ---- self-attention x + y (fused dual-stream) ----
        gemm_ca<128,2><<<dim3(18, 16, 2), 256, SMEM_CA128>>>(
            gxt, gxt, gyt, gyt, axw, ayw, axb, ayb, gqkv, D, D, QS);
        attn_fused<<<dim3(BB * H, SQ / 64, 2), 256, ATT_SMEM>>>(gqkv, xmask, ymask, gh);
        addln_kernel<<<2 * M, 256>>>(
            gx, gh, lnx_g + 0 * D, lnx_b + 0 * D, gxt,
            gy, gh + MD, lny_g + 0 * D, lny_b + 0 * D, gyt);

        // ---- cross x (q from x, kv from updated y) ----
        gemm_ca<128,2><<<dim3(18, 16, 1), 256, SMEM_CA128>>>(
            gxt, gyt, gxt, gyt, cxw, cxw, cxb, cxb, gqkv, D, D, QS);
        attn_fused<<<dim3(BB * H, SQ / 64, 1), 256, ATT_SMEM>>>(gqkv, ymask, ymask, gh);
        addln_kernel<<<M, 256>>>(
            gx, gh, lnx_g + 1 * D, lnx_b + 1 * D, gxt,
            gx, gh, lnx_g + 1 * D, lnx_b + 1 * D, gxt);

        // ---- cross y (q from y, kv from updated x) ----
        gemm_ca<128,2><<<dim3(18, 16, 1), 256, SMEM_CA128>>>(
            gyt, gxt, gyt, gxt, cyw, cyw, cyb, cyb, gqkv, D, D, QS);
        attn_fused<<<dim3(BB * H, SQ / 64, 1), 256, ATT_SMEM>>>(gqkv, xmask, xmask, gh);
        addln_kernel<<<M, 256>>>(
            gy, gh, lny_g + 1 * D, lny_b + 1 * D, gyt,
            gy, gh, lny_g + 1 * D, lny_b + 1 * D, gyt);

        // ---- FFN x + y (fused dual-stream) ----
        gemm_ca<128,1><<<dim3(FF / 128, 16, 2), 256, SMEM_CA128>>>(
            gxt, gxt, gyt, gyt, fxw1, fyw1, fxb1, fyb1, gffn, FF, D, (size_t)M * FF);
        gemm_ca<64,0><<<dim3(D / 64, 16, 2), 256, SMEM_CA64>>>(
            gffn, gffn, gffn + (size_t)M * FF, gffn + (size_t)M * FF,
            fxw2, fyw2, fxb2, fyb2, gh, D, FF, MD);
        addln_kernel<<<2 * M, 256>>>(
            gx, gh, lnx_g + 2 * D, lnx_b + 2 * D, gxt,
            gy, gh + MD, lny_g + 2 * D, lny_b + 2 * D, gyt);
    }

    cudaMemcpyAsync((float*)d_out,      gx, MD * sizeof(float), cudaMemcpyDeviceToDevice, 0);
    cudaMemcpyAsync((float*)d_out + MD, gy, MD * sizeof(float), cudaMemcpyDeviceToDevice, 0);
}